// round 1
// baseline (speedup 1.0000x reference)
#include <cuda_runtime.h>
#include <math.h>

#define NBANKS 16
#define D 32
#define NIN 3072
#define NOUT 1000
#define BATCH 8192
#define NEDGE 54
#define BN_EPS 1e-5f

// ---------------- device scratch (globals; no allocation allowed) ----------
__device__ float g_px1[64 * NIN];
__device__ float g_px2[64 * NIN];
__device__ float g_scale[NIN];
__device__ float g_shift[NIN];
__device__ float g_Wp[NIN * 64];        // folded input weights, [c][64]
__device__ float g_bp[64];              // folded input bias
__device__ float g_in1[BATCH * D];      // un-normalized input act of bank 1
__device__ float g_pre[NBANKS * BATCH * D]; // post-relu, pre-BN acts per bank
__device__ float g_mean[NBANKS * D];
__device__ float g_rstd[NBANKS * D];
__device__ float g_part1[64 * D];
__device__ float g_part2[64 * D];
__device__ float g_tg_fallback[BATCH];

// ---------------- small utility kernels ------------------------------------
__global__ void zero_tg_kernel(float* tg) {
    int i = blockIdx.x * 256 + threadIdx.x;
    if (i < BATCH) tg[i] = 0.f;
}

// column stats of x, partial over 128-row chunks. grid (12, 64), 256 thr.
__global__ void xstats_partial_kernel(const float* __restrict__ x) {
    int col = blockIdx.x * 256 + threadIdx.x;
    int chunk = blockIdx.y;
    float s1 = 0.f, s2 = 0.f;
    int r0 = chunk * 128;
    #pragma unroll 4
    for (int r = r0; r < r0 + 128; r++) {
        float v = x[(size_t)r * NIN + col];
        s1 += v;
        s2 += v * v;
    }
    g_px1[chunk * NIN + col] = s1;
    g_px2[chunk * NIN + col] = s2;
}

// finalize x stats; fold gamma/beta into per-column scale/shift. grid 12x256.
__global__ void xfinal_kernel(const float* __restrict__ gamma,
                              const float* __restrict__ beta) {
    int col = blockIdx.x * 256 + threadIdx.x;
    float s1 = 0.f, s2 = 0.f;
    #pragma unroll 8
    for (int c = 0; c < 64; c++) {
        s1 += g_px1[c * NIN + col];
        s2 += g_px2[c * NIN + col];
    }
    float mean = s1 * (1.f / BATCH);
    float var = s2 * (1.f / BATCH) - mean * mean;
    float rstd = rsqrtf(var + BN_EPS);
    float sc = rstd * gamma[col];
    g_scale[col] = sc;
    g_shift[col] = beta[col] - mean * sc;
}

// W'[c][k*32+d] = scale[c] * W_in[k][c][d].  grid 768x256.
__global__ void foldw_kernel(const float* __restrict__ W_in) {
    int gid = blockIdx.x * 256 + threadIdx.x;
    if (gid >= NIN * 64) return;
    int c = gid >> 6;
    int j = gid & 63;
    int k = j >> 5;
    int d = j & 31;
    g_Wp[gid] = g_scale[c] * W_in[(size_t)k * NIN * D + c * D + d];
}

// b'[j] = b_in[j] + sum_c shift[c] * W_in[k][c][d].  grid 64 blocks x 256 thr.
__global__ void foldb_kernel(const float* __restrict__ W_in,
                             const float* __restrict__ b_in) {
    __shared__ float red[256];
    int j = blockIdx.x;      // 0..63
    int k = j >> 5;
    int d = j & 31;
    float s = 0.f;
    for (int c = threadIdx.x; c < NIN; c += 256)
        s += g_shift[c] * W_in[(size_t)k * NIN * D + c * D + d];
    red[threadIdx.x] = s;
    __syncthreads();
    for (int off = 128; off; off >>= 1) {
        if (threadIdx.x < off) red[threadIdx.x] += red[threadIdx.x + off];
        __syncthreads();
    }
    if (threadIdx.x == 0) g_bp[j] = b_in[j] + red[0];
}

// ---------------- input GEMM: relu(x @ W' + b') ----------------------------
// tile 64x64, K=3072, TK=32. grid 128 blocks, 256 threads.
__global__ void gemm_in_kernel(const float* __restrict__ x) {
    __shared__ float As[64][33];
    __shared__ float Bs[32][64];
    int tid = threadIdx.x;
    int tx = tid & 15, ty = tid >> 4;
    int rowBase = blockIdx.x * 64;
    float c[4][4] = {};
    for (int kb = 0; kb < NIN; kb += 32) {
        #pragma unroll
        for (int p = 0; p < 8; p++) {
            int i = p * 8 + (tid >> 5);
            int j = tid & 31;
            As[i][j] = x[(size_t)(rowBase + i) * NIN + kb + j];
        }
        #pragma unroll
        for (int p = 0; p < 8; p++) {
            int k = p * 4 + (tid >> 6);
            int j = tid & 63;
            Bs[k][j] = g_Wp[(kb + k) * 64 + j];
        }
        __syncthreads();
        #pragma unroll
        for (int k = 0; k < 32; k++) {
            float a[4], b[4];
            #pragma unroll
            for (int i = 0; i < 4; i++) a[i] = As[ty * 4 + i][k];
            #pragma unroll
            for (int j = 0; j < 4; j++) b[j] = Bs[k][tx * 4 + j];
            #pragma unroll
            for (int i = 0; i < 4; i++)
                #pragma unroll
                for (int j = 0; j < 4; j++) c[i][j] += a[i] * b[j];
        }
        __syncthreads();
    }
    #pragma unroll
    for (int i = 0; i < 4; i++) {
        int r = rowBase + ty * 4 + i;
        #pragma unroll
        for (int j = 0; j < 4; j++) {
            int col = tx * 4 + j;
            float v = fmaxf(c[i][j] + g_bp[col], 0.f);
            if (col < 32) g_pre[r * D + col] = v;            // bank 0
            else          g_in1[r * D + (col - 32)] = v;     // bank 1 pre-edge
        }
    }
}

// ---------------- bank kernel ----------------------------------------------
// grid 64 blocks x 256 thr (8 warps x 16 rows). Computes pre[t] (post-relu,
// pre-BN), accumulates total_gate, writes per-block column stats partials.
__global__ void bank_kernel(int t, int estart, int ecount, int s0,
                            const float* __restrict__ Wg,
                            const float* __restrict__ Wd,
                            const float* __restrict__ bd,
                            float* __restrict__ tg) {
    __shared__ float sWd[4][1024];
    __shared__ float sWg[4][32], sbd[4][32], smn[4][32], srs[4][32];
    int tid = threadIdx.x;
    for (int ei = 0; ei < ecount; ei++) {
        int e = estart + ei;
        for (int p = tid; p < 1024; p += 256) sWd[ei][p] = Wd[e * 1024 + p];
        if (tid < 32) {
            sWg[ei][tid] = Wg[e * 32 + tid];
            sbd[ei][tid] = bd[e * 32 + tid];
            smn[ei][tid] = g_mean[(s0 + ei) * 32 + tid];
            srs[ei][tid] = g_rstd[(s0 + ei) * 32 + tid];
        }
    }
    __syncthreads();
    int warp = tid >> 5, lane = tid & 31;
    float s1 = 0.f, s2 = 0.f;
    int rbase = blockIdx.x * 128 + warp * 16;
    for (int rr = 0; rr < 16; rr++) {
        int r = rbase + rr;
        float acc;
        if (t == 0)      acc = g_pre[r * D + lane];
        else if (t == 1) acc = g_in1[r * D + lane];
        else             acc = 0.f;
        float tgs = 0.f;
        for (int ei = 0; ei < ecount; ei++) {
            int s = s0 + ei;
            float a = (g_pre[s * BATCH * D + r * D + lane] - smn[ei][lane]) * srs[ei][lane];
            float g = a * sWg[ei][lane];
            #pragma unroll
            for (int off = 16; off; off >>= 1)
                g += __shfl_xor_sync(0xffffffffu, g, off);
            g = fminf(fmaxf(g, 0.f), 1.f);
            tgs += g;
            float data = sbd[ei][lane];
            #pragma unroll
            for (int k = 0; k < 32; k++) {
                float ak = __shfl_sync(0xffffffffu, a, k);
                data += ak * sWd[ei][k * 32 + lane];
            }
            acc += g * data;
        }
        float v = fmaxf(acc, 0.f);
        g_pre[t * BATCH * D + r * D + lane] = v;
        if (ecount && lane == 0) tg[r] += tgs;
        s1 += v;
        s2 += v * v;
    }
    __shared__ float red1[8][32], red2[8][32];
    red1[warp][lane] = s1;
    red2[warp][lane] = s2;
    __syncthreads();
    if (warp == 0) {
        float a = 0.f, b = 0.f;
        #pragma unroll
        for (int w = 0; w < 8; w++) { a += red1[w][lane]; b += red2[w][lane]; }
        g_part1[blockIdx.x * 32 + lane] = a;
        g_part2[blockIdx.x * 32 + lane] = b;
    }
}

// reduce the 64 partials -> mean/rstd for bank t. 1 block, 32 threads.
__global__ void stats_final_kernel(int t) {
    int d = threadIdx.x;
    float s1 = 0.f, s2 = 0.f;
    #pragma unroll 8
    for (int b = 0; b < 64; b++) {
        s1 += g_part1[b * 32 + d];
        s2 += g_part2[b * 32 + d];
    }
    float mean = s1 * (1.f / BATCH);
    float var = s2 * (1.f / BATCH) - mean * mean;
    g_mean[t * 32 + d] = mean;
    g_rstd[t * 32 + d] = rsqrtf(var + BN_EPS);
}

// ---------------- output GEMM ----------------------------------------------
// out[8192,1000] = norm(pre14)@Wout0 + norm(pre15)@Wout1.
// tile 64x64, K=64 (full). grid (128, 16), 256 threads.
__global__ void gemm_out_kernel(const float* __restrict__ Wout,
                                float* __restrict__ out) {
    __shared__ float As[64][65];
    __shared__ float Bs[64][64];
    __shared__ float sm[64], sr[64];
    int tid = threadIdx.x;
    int tx = tid & 15, ty = tid >> 4;
    int rowBase = blockIdx.x * 64;
    int colBase = blockIdx.y * 64;
    if (tid < 64) {
        int bank = 14 + (tid >> 5), d = tid & 31;
        sm[tid] = g_mean[bank * 32 + d];
        sr[tid] = g_rstd[bank * 32 + d];
    }
    __syncthreads();
    #pragma unroll
    for (int p = 0; p < 16; p++) {
        int idx = p * 256 + tid;
        int i = idx >> 6, kk = idx & 63;
        int bank = 14 + (kk >> 5), d = kk & 31;
        float v = g_pre[bank * BATCH * D + (rowBase + i) * D + d];
        As[i][kk] = (v - sm[kk]) * sr[kk];
    }
    #pragma unroll
    for (int p = 0; p < 16; p++) {
        int idx = p * 256 + tid;
        int k = idx >> 6, j = idx & 63;
        int n = colBase + j;
        int bank = k >> 5, d = k & 31;
        Bs[k][j] = (n < NOUT) ? Wout[(size_t)bank * D * NOUT + d * NOUT + n] : 0.f;
    }
    __syncthreads();
    float c[4][4] = {};
    #pragma unroll
    for (int k = 0; k < 64; k++) {
        float a[4], b[4];
        #pragma unroll
        for (int i = 0; i < 4; i++) a[i] = As[ty * 4 + i][k];
        #pragma unroll
        for (int j = 0; j < 4; j++) b[j] = Bs[k][tx * 4 + j];
        #pragma unroll
        for (int i = 0; i < 4; i++)
            #pragma unroll
            for (int j = 0; j < 4; j++) c[i][j] += a[i] * b[j];
    }
    #pragma unroll
    for (int i = 0; i < 4; i++) {
        int r = rowBase + ty * 4 + i;
        #pragma unroll
        for (int j = 0; j < 4; j++) {
            int n = colBase + tx * 4 + j;
            if (n < NOUT) out[(size_t)r * NOUT + n] = c[i][j];
        }
    }
}

// ---------------- launch ----------------------------------------------------
extern "C" void kernel_launch(void* const* d_in, const int* in_sizes, int n_in,
                              void* d_out, int out_size) {
    const float* x     = (const float*)d_in[0];
    const float* gamma = (const float*)d_in[1];
    const float* beta  = (const float*)d_in[2];
    const float* W_in  = (const float*)d_in[3];
    const float* b_in  = (const float*)d_in[4];
    const float* Wg    = (const float*)d_in[5];
    const float* Wd    = (const float*)d_in[6];
    const float* bd    = (const float*)d_in[7];
    const float* Wout  = (const float*)d_in[8];
    float* out = (float*)d_out;

    // total_gate destination: tail of d_out if present, else scratch.
    float* tg;
    if (out_size >= BATCH * NOUT + BATCH) {
        tg = out + (size_t)BATCH * NOUT;
    } else {
        void* p = nullptr;
        cudaGetSymbolAddress(&p, g_tg_fallback);
        tg = (float*)p;
    }

    zero_tg_kernel<<<32, 256>>>(tg);
    xstats_partial_kernel<<<dim3(12, 64), 256>>>(x);
    xfinal_kernel<<<12, 256>>>(gamma, beta);
    foldw_kernel<<<768, 256>>>(W_in);
    foldb_kernel<<<64, 256>>>(W_in, b_in);
    gemm_in_kernel<<<128, 256>>>(x);

    for (int t = 0; t < NBANKS; t++) {
        int estart, ecount, s0;
        if (t == 0)      { estart = 0;  ecount = 0; s0 = 0; }
        else if (t <= 4) { ecount = t;  s0 = 0;
                           estart = (t == 1) ? 0 : (t == 2) ? 1 : (t == 3) ? 3 : 6; }
        else             { estart = 10 + (t - 5) * 4; ecount = 4; s0 = t - 4; }
        bank_kernel<<<64, 256>>>(t, estart, ecount, s0, Wg, Wd, bd, tg);
        stats_final_kernel<<<1, 32>>>(t);
    }

    gemm_out_kernel<<<dim3(128, 16), 256>>>(Wout, out);
}

// round 2
// speedup vs baseline: 2.6923x; 2.6923x over previous
#include <cuda_runtime.h>
#include <math.h>

#define NBANKS 16
#define D 32
#define NIN 3072
#define NOUT 1000
#define BATCH 8192
#define BN_EPS 1e-5f
#define CB 128            // chain blocks (all co-resident: 128 <= 148 SMs)

// ---------------- device scratch ----------------
__device__ float g_px1[64 * NIN];
__device__ float g_px2[64 * NIN];
__device__ float g_scale[NIN];
__device__ float g_shift[NIN];
__device__ float g_Wp[NIN * 64];      // folded input weights, [c][64]
__device__ float g_bp[64];            // folded input bias
__device__ float g_in0[BATCH * D];    // input act bank 0 (post-relu)
__device__ float g_in1[BATCH * D];    // input act bank 1 (post-relu)
__device__ float g_preT[2 * D * BATCH]; // banks 14,15 post-relu pre-BN, [bank][d][row]
__device__ float g_mean[NBANKS * D];
__device__ float g_rstd[NBANKS * D];
__device__ float g_p1s[NBANKS * CB * 32];
__device__ float g_p2s[NBANKS * CB * 32];
__device__ unsigned g_barc;
__device__ unsigned g_barg;
__device__ float g_tg_fallback[BATCH];

// ---------------- x stats + weight folding ----------------
__global__ void xstats_partial_kernel(const float* __restrict__ x) {
    int col = blockIdx.x * 256 + threadIdx.x;
    int chunk = blockIdx.y;
    float s1 = 0.f, s2 = 0.f;
    int r0 = chunk * 128;
    #pragma unroll 4
    for (int r = r0; r < r0 + 128; r++) {
        float v = x[(size_t)r * NIN + col];
        s1 += v; s2 += v * v;
    }
    g_px1[chunk * NIN + col] = s1;
    g_px2[chunk * NIN + col] = s2;
}

__global__ void xfinal_kernel(const float* __restrict__ gamma,
                              const float* __restrict__ beta) {
    int col = blockIdx.x * 256 + threadIdx.x;
    float s1 = 0.f, s2 = 0.f;
    #pragma unroll 8
    for (int c = 0; c < 64; c++) { s1 += g_px1[c * NIN + col]; s2 += g_px2[c * NIN + col]; }
    float mean = s1 * (1.f / BATCH);
    float var = s2 * (1.f / BATCH) - mean * mean;
    float rstd = rsqrtf(var + BN_EPS);
    float sc = rstd * gamma[col];
    g_scale[col] = sc;
    g_shift[col] = beta[col] - mean * sc;
}

__global__ void foldw_kernel(const float* __restrict__ W_in) {
    int gid = blockIdx.x * 256 + threadIdx.x;
    if (gid >= NIN * 64) return;
    int c = gid >> 6;
    int j = gid & 63;
    int k = j >> 5, d = j & 31;
    g_Wp[gid] = g_scale[c] * W_in[(size_t)k * NIN * D + c * D + d];
}

__global__ void foldb_kernel(const float* __restrict__ W_in,
                             const float* __restrict__ b_in) {
    __shared__ float red[256];
    int j = blockIdx.x;
    int k = j >> 5, d = j & 31;
    float s = 0.f;
    for (int c = threadIdx.x; c < NIN; c += 256)
        s += g_shift[c] * W_in[(size_t)k * NIN * D + c * D + d];
    red[threadIdx.x] = s;
    __syncthreads();
    for (int off = 128; off; off >>= 1) {
        if (threadIdx.x < off) red[threadIdx.x] += red[threadIdx.x + off];
        __syncthreads();
    }
    if (threadIdx.x == 0) g_bp[j] = b_in[j] + red[0];
}

// ---------------- input GEMM: relu(x @ W' + b') ----------------
// 64x64 tile, K-tile 32, k-major smem, 4x4 microtile. grid 128, 256 thr.
__global__ void __launch_bounds__(256) gemm_in_kernel(const float* __restrict__ x) {
    __shared__ float AsT[32 * 68];   // [k][row], pad 68
    __shared__ float Bs[32 * 64];    // [k][col]
    int tid = threadIdx.x;
    int tx = tid & 15, ty = tid >> 4;
    int rowBase = blockIdx.x * 64;
    float c[4][4] = {};
    for (int kb = 0; kb < NIN; kb += 32) {
        #pragma unroll
        for (int p = 0; p < 2; p++) {
            int f4i = p * 256 + tid;
            int row = f4i >> 3, kq = (f4i & 7) * 4;
            float4 v = *(const float4*)&x[(size_t)(rowBase + row) * NIN + kb + kq];
            AsT[(kq + 0) * 68 + row] = v.x;
            AsT[(kq + 1) * 68 + row] = v.y;
            AsT[(kq + 2) * 68 + row] = v.z;
            AsT[(kq + 3) * 68 + row] = v.w;
        }
        #pragma unroll
        for (int p = 0; p < 8; p++) {
            int idx = p * 256 + tid;
            Bs[idx] = g_Wp[(kb + (idx >> 6)) * 64 + (idx & 63)];
        }
        __syncthreads();
        #pragma unroll
        for (int k = 0; k < 32; k++) {
            float4 a4 = *(const float4*)&AsT[k * 68 + ty * 4];
            float4 b4 = *(const float4*)&Bs[k * 64 + tx * 4];
            float a[4] = {a4.x, a4.y, a4.z, a4.w};
            float b[4] = {b4.x, b4.y, b4.z, b4.w};
            #pragma unroll
            for (int i = 0; i < 4; i++)
                #pragma unroll
                for (int j = 0; j < 4; j++) c[i][j] += a[i] * b[j];
        }
        __syncthreads();
    }
    #pragma unroll
    for (int i = 0; i < 4; i++) {
        int r = rowBase + ty * 4 + i;
        #pragma unroll
        for (int j = 0; j < 4; j++) {
            int col = tx * 4 + j;
            float v = fmaxf(c[i][j] + g_bp[col], 0.f);
            if (col < 32) g_in0[r * D + col] = v;
            else          g_in1[r * D + (col - 32)] = v;
        }
    }
}

// ---------------- persistent bank-chain kernel ----------------
__device__ __forceinline__ void grid_bar() {
    __syncthreads();
    if (threadIdx.x == 0) {
        unsigned gen = *(volatile unsigned*)&g_barg;
        __threadfence();
        if (atomicAdd(&g_barc, 1u) == gridDim.x - 1) {
            atomicExch(&g_barc, 0u);
            __threadfence();
            *(volatile unsigned*)&g_barg = gen + 1;
        } else {
            while (*(volatile unsigned*)&g_barg == gen) { }
        }
        __threadfence();
    }
    __syncthreads();
}

__global__ void __launch_bounds__(256, 1) chain_kernel(
    const float* __restrict__ Wg, const float* __restrict__ Wd,
    const float* __restrict__ bd, float* __restrict__ tg) {
    __shared__ float actT[4][32][68];   // rolling window, [slot][d][row] pad 68
    __shared__ float sWd[32 * 32];      // BN-folded Wd' for current edge
    __shared__ float sbd[32];
    __shared__ float sWgv[32];
    __shared__ float sgate[64];
    __shared__ float stg[64];
    __shared__ float smean[16][32];
    __shared__ float srstd[16][32];
    __shared__ float red1[8][32];
    __shared__ float red2[8][32];
    __shared__ float sgb;

    int tid = threadIdx.x;
    int blk = blockIdx.x;
    int rowBase = blk * 64;
    int jx = tid & 15, ry = tid >> 4;
    int j0 = jx * 2, r0 = ry * 4;
    int warp = tid >> 5, lane = tid & 31;
    if (tid < 64) stg[tid] = 0.f;

    for (int t = 0; t < 16; t++) {
        float acc[4][2];
        if (t <= 1) {
            const float* src = (t == 0) ? g_in0 : g_in1;
            #pragma unroll
            for (int i = 0; i < 4; i++) {
                float2 v = *(const float2*)&src[(rowBase + r0 + i) * D + j0];
                acc[i][0] = v.x; acc[i][1] = v.y;
            }
        } else {
            #pragma unroll
            for (int i = 0; i < 4; i++) { acc[i][0] = 0.f; acc[i][1] = 0.f; }
        }
        int s0 = (t - 4 < 0) ? 0 : t - 4;
        int ecnt = (t < 4) ? t : 4;
        int ebase = (t <= 1) ? 0 : (t == 2) ? 1 : (t == 3) ? 3 : (t == 4) ? 6 : 10 + (t - 5) * 4;

        for (int ei = 0; ei < ecnt; ei++) {
            int e = ebase + ei, s = s0 + ei, slot = s & 3;
            // stage 1: fold BN into edge weights
            #pragma unroll
            for (int p = 0; p < 4; p++) {
                int idx = p * 256 + tid;
                sWd[idx] = Wd[e * 1024 + idx] * srstd[s][idx >> 5];
            }
            if (tid < 32) sWgv[tid] = Wg[e * 32 + tid] * srstd[s][tid];
            __syncthreads();
            // stage 2: folded biases + raw gate sums
            if (warp == 0) {
                float sum = 0.f;
                #pragma unroll
                for (int k = 0; k < 32; k++) sum += smean[s][k] * sWd[k * 32 + lane];
                sbd[lane] = bd[e * 32 + lane] - sum;
            } else if (warp == 1) {
                float v = smean[s][lane] * sWgv[lane];
                #pragma unroll
                for (int o = 16; o; o >>= 1) v += __shfl_xor_sync(~0u, v, o);
                if (lane == 0) sgb = -v;
            } else if (warp < 4) {
                int row = (warp - 2) * 32 + lane;
                float g = 0.f;
                #pragma unroll
                for (int k = 0; k < 32; k++) g += actT[slot][k][row] * sWgv[k];
                sgate[row] = g;
            }
            __syncthreads();
            // stage 3: gated mini-GEMM, 4 rows x 2 cols per thread
            float gb = sgb;
            float gi[4];
            #pragma unroll
            for (int i = 0; i < 4; i++)
                gi[i] = fminf(fmaxf(sgate[r0 + i] + gb, 0.f), 1.f);
            if (tid < 64) stg[tid] += fminf(fmaxf(sgate[tid] + gb, 0.f), 1.f);
            float dat[4][2];
            #pragma unroll
            for (int i = 0; i < 4; i++) { dat[i][0] = sbd[j0]; dat[i][1] = sbd[j0 + 1]; }
            #pragma unroll
            for (int k = 0; k < 32; k++) {
                float4 a4 = *(const float4*)&actT[slot][k][r0];
                float w0 = sWd[k * 32 + j0], w1 = sWd[k * 32 + j0 + 1];
                dat[0][0] += a4.x * w0; dat[0][1] += a4.x * w1;
                dat[1][0] += a4.y * w0; dat[1][1] += a4.y * w1;
                dat[2][0] += a4.z * w0; dat[2][1] += a4.z * w1;
                dat[3][0] += a4.w * w0; dat[3][1] += a4.w * w1;
            }
            #pragma unroll
            for (int i = 0; i < 4; i++) {
                acc[i][0] += gi[i] * dat[i][0];
                acc[i][1] += gi[i] * dat[i][1];
            }
            __syncthreads();
        }

        // relu + store transposed into rolling slot (slot of bank t-4 is dead now)
        float v[4][2];
        #pragma unroll
        for (int i = 0; i < 4; i++) {
            v[i][0] = fmaxf(acc[i][0], 0.f);
            v[i][1] = fmaxf(acc[i][1], 0.f);
        }
        int slot_t = t & 3;
        #pragma unroll
        for (int cc = 0; cc < 2; cc++) {
            float4 st = make_float4(v[0][cc], v[1][cc], v[2][cc], v[3][cc]);
            *(float4*)&actT[slot_t][j0 + cc][r0] = st;
            if (t >= 14)
                *(float4*)&g_preT[((t - 14) * D + j0 + cc) * BATCH + rowBase + r0] = st;
        }
        __syncthreads();
        // per-block column stats partials
        {
            float s1 = 0.f, s2 = 0.f;
            #pragma unroll
            for (int q = 0; q < 8; q++) {
                float xv = actT[slot_t][lane][warp * 8 + q];
                s1 += xv; s2 += xv * xv;
            }
            red1[warp][lane] = s1;
            red2[warp][lane] = s2;
        }
        __syncthreads();
        if (warp == 0) {
            float s1 = 0.f, s2 = 0.f;
            #pragma unroll
            for (int g2 = 0; g2 < 8; g2++) { s1 += red1[g2][lane]; s2 += red2[g2][lane]; }
            g_p1s[(t * CB + blk) * 32 + lane] = s1;
            g_p2s[(t * CB + blk) * 32 + lane] = s2;
        }
        __threadfence();
        grid_bar();
        // finalize bank-t stats (every block, redundantly, from L2)
        if (warp < 4) {
            float s1 = 0.f, s2 = 0.f;
            #pragma unroll 8
            for (int b = warp; b < CB; b += 4) {
                s1 += __ldcg(&g_p1s[(t * CB + b) * 32 + lane]);
                s2 += __ldcg(&g_p2s[(t * CB + b) * 32 + lane]);
            }
            red1[warp][lane] = s1;
            red2[warp][lane] = s2;
        }
        __syncthreads();
        if (warp == 0) {
            float s1 = red1[0][lane] + red1[1][lane] + red1[2][lane] + red1[3][lane];
            float s2 = red2[0][lane] + red2[1][lane] + red2[2][lane] + red2[3][lane];
            float mean = s1 * (1.f / BATCH);
            float var = s2 * (1.f / BATCH) - mean * mean;
            float rs = rsqrtf(var + BN_EPS);
            smean[t][lane] = mean;
            srstd[t][lane] = rs;
            if (blk == 0) { g_mean[t * 32 + lane] = mean; g_rstd[t * 32 + lane] = rs; }
        }
        __syncthreads();
    }
    if (tid < 64) tg[rowBase + tid] = stg[tid];
}

// ---------------- output GEMM ----------------
// out = norm(pre14)@Wout0 + norm(pre15)@Wout1. K=64. grid (128,16), 256 thr.
__global__ void __launch_bounds__(256) gemm_out_kernel(const float* __restrict__ Wout,
                                                       float* __restrict__ out) {
    __shared__ float AsT[64 * 68];   // [k][row]
    __shared__ float Bs[64 * 64];    // [k][col]
    __shared__ float sm[64], sr[64];
    int tid = threadIdx.x;
    int tx = tid & 15, ty = tid >> 4;
    int rowBase = blockIdx.x * 64;
    int colBase = blockIdx.y * 64;
    if (tid < 64) {
        int bank = 14 + (tid >> 5), d = tid & 31;
        sm[tid] = g_mean[bank * 32 + d];
        sr[tid] = g_rstd[bank * 32 + d];
    }
    __syncthreads();
    #pragma unroll
    for (int p = 0; p < 16; p++) {
        int idx = p * 256 + tid;
        int kk = idx >> 6, i = idx & 63;
        float v = g_preT[kk * BATCH + rowBase + i];
        AsT[kk * 68 + i] = (v - sm[kk]) * sr[kk];
    }
    #pragma unroll
    for (int p = 0; p < 16; p++) {
        int idx = p * 256 + tid;
        int k = idx >> 6, j = idx & 63;
        int n = colBase + j;
        int bank = k >> 5, d = k & 31;
        Bs[idx] = (n < NOUT) ? Wout[(size_t)bank * D * NOUT + d * NOUT + n] : 0.f;
    }
    __syncthreads();
    float c[4][4] = {};
    #pragma unroll
    for (int k = 0; k < 64; k++) {
        float4 a4 = *(const float4*)&AsT[k * 68 + ty * 4];
        float4 b4 = *(const float4*)&Bs[k * 64 + tx * 4];
        float a[4] = {a4.x, a4.y, a4.z, a4.w};
        float b[4] = {b4.x, b4.y, b4.z, b4.w};
        #pragma unroll
        for (int i = 0; i < 4; i++)
            #pragma unroll
            for (int j = 0; j < 4; j++) c[i][j] += a[i] * b[j];
    }
    #pragma unroll
    for (int i = 0; i < 4; i++) {
        int r = rowBase + ty * 4 + i;
        #pragma unroll
        for (int j = 0; j < 4; j++) {
            int n = colBase + tx * 4 + j;
            if (n < NOUT) out[(size_t)r * NOUT + n] = c[i][j];
        }
    }
}

// ---------------- launch ----------------
extern "C" void kernel_launch(void* const* d_in, const int* in_sizes, int n_in,
                              void* d_out, int out_size) {
    const float* x     = (const float*)d_in[0];
    const float* gamma = (const float*)d_in[1];
    const float* beta  = (const float*)d_in[2];
    const float* W_in  = (const float*)d_in[3];
    const float* b_in  = (const float*)d_in[4];
    const float* Wg    = (const float*)d_in[5];
    const float* Wd    = (const float*)d_in[6];
    const float* bd    = (const float*)d_in[7];
    const float* Wout  = (const float*)d_in[8];
    float* out = (float*)d_out;

    float* tg;
    if (out_size >= BATCH * NOUT + BATCH) {
        tg = out + (size_t)BATCH * NOUT;
    } else {
        void* p = nullptr;
        cudaGetSymbolAddress(&p, g_tg_fallback);
        tg = (float*)p;
    }

    xstats_partial_kernel<<<dim3(12, 64), 256>>>(x);
    xfinal_kernel<<<12, 256>>>(gamma, beta);
    foldw_kernel<<<768, 256>>>(W_in);
    foldb_kernel<<<64, 256>>>(W_in, b_in);
    gemm_in_kernel<<<128, 256>>>(x);
    chain_kernel<<<CB, 256>>>(Wg, Wd, bd, tg);
    gemm_out_kernel<<<dim3(128, 16), 256>>>(Wout, out);
}

// round 4
// speedup vs baseline: 3.0523x; 1.1337x over previous
#include <cuda_runtime.h>
#include <cuda_bf16.h>
#include <stdint.h>
#include <math.h>

#define NBANKS 16
#define D 32
#define NIN 3072
#define NOUT 1000
#define BATCH 8192
#define BN_EPS 1e-5f
#define CB 128

// ---------------- device scratch ----------------
__device__ float g_px1[64 * NIN];
__device__ float g_px2[64 * NIN];
__device__ float g_scale[NIN];
__device__ float g_shift[NIN];
__device__ __nv_bfloat16 g_WpH[NIN * 64];   // folded input weights hi
__device__ __nv_bfloat16 g_WpL[NIN * 64];   // folded input weights lo
__device__ float g_bp[64];
__device__ float g_in0[BATCH * D];
__device__ float g_in1[BATCH * D];
__device__ __nv_bfloat16 g_preTH[64 * BATCH];  // banks14,15 raw acts, [k][row]
__device__ __nv_bfloat16 g_preTL[64 * BATCH];
__device__ __nv_bfloat16 g_WoutH[64 * 1024];   // BN-folded Wout, [k][n] pad 1024
__device__ __nv_bfloat16 g_WoutL[64 * 1024];
__device__ float g_bout[1024];
__device__ float g_mean[NBANKS * D];
__device__ float g_rstd[NBANKS * D];
__device__ float g_p1s[NBANKS * CB * 32];
__device__ float g_p2s[NBANKS * CB * 32];
__device__ unsigned g_barc;
__device__ unsigned g_barg;
__device__ float g_tg_fallback[BATCH];

// ---------------- helpers ----------------
__device__ __forceinline__ unsigned smem_u32(const void* p) {
    return (unsigned)__cvta_generic_to_shared(p);
}
__device__ __forceinline__ void ldsm_x4(unsigned& r0, unsigned& r1, unsigned& r2,
                                        unsigned& r3, unsigned addr) {
    asm volatile("ldmatrix.sync.aligned.m8n8.x4.shared.b16 {%0,%1,%2,%3},[%4];"
                 : "=r"(r0), "=r"(r1), "=r"(r2), "=r"(r3) : "r"(addr));
}
__device__ __forceinline__ void ldsm_x4_t(unsigned& r0, unsigned& r1, unsigned& r2,
                                          unsigned& r3, unsigned addr) {
    asm volatile("ldmatrix.sync.aligned.m8n8.x4.trans.shared.b16 {%0,%1,%2,%3},[%4];"
                 : "=r"(r0), "=r"(r1), "=r"(r2), "=r"(r3) : "r"(addr));
}
__device__ __forceinline__ void mma_bf16(float* c, const unsigned* a,
                                         unsigned b0, unsigned b1) {
    asm volatile(
        "mma.sync.aligned.m16n8k16.row.col.f32.bf16.bf16.f32 "
        "{%0,%1,%2,%3},{%4,%5,%6,%7},{%8,%9},{%0,%1,%2,%3};"
        : "+f"(c[0]), "+f"(c[1]), "+f"(c[2]), "+f"(c[3])
        : "r"(a[0]), "r"(a[1]), "r"(a[2]), "r"(a[3]), "r"(b0), "r"(b1));
}
__device__ __forceinline__ unsigned pack_hi2(float x, float y) {
    __nv_bfloat16 hx = __float2bfloat16(x), hy = __float2bfloat16(y);
    return ((unsigned)__bfloat16_as_ushort(hy) << 16) | __bfloat16_as_ushort(hx);
}
__device__ __forceinline__ unsigned pack_lo2(float x, float y) {
    __nv_bfloat16 hx = __float2bfloat16(x), hy = __float2bfloat16(y);
    float lx = x - __bfloat162float(hx), ly = y - __bfloat162float(hy);
    __nv_bfloat16 bx = __float2bfloat16(lx), by = __float2bfloat16(ly);
    return ((unsigned)__bfloat16_as_ushort(by) << 16) | __bfloat16_as_ushort(bx);
}

// ---------------- x stats + folds ----------------
__global__ void xstats_partial_kernel(const float* __restrict__ x) {
    int col = blockIdx.x * 256 + threadIdx.x;
    int chunk = blockIdx.y;
    float s1 = 0.f, s2 = 0.f;
    int r0 = chunk * 128;
    #pragma unroll 4
    for (int r = r0; r < r0 + 128; r++) {
        float v = x[(size_t)r * NIN + col];
        s1 += v; s2 += v * v;
    }
    g_px1[chunk * NIN + col] = s1;
    g_px2[chunk * NIN + col] = s2;
}

__global__ void xfinal_kernel(const float* __restrict__ gamma,
                              const float* __restrict__ beta) {
    int col = blockIdx.x * 256 + threadIdx.x;
    float s1 = 0.f, s2 = 0.f;
    #pragma unroll 8
    for (int c = 0; c < 64; c++) { s1 += g_px1[c * NIN + col]; s2 += g_px2[c * NIN + col]; }
    float mean = s1 * (1.f / BATCH);
    float var = s2 * (1.f / BATCH) - mean * mean;
    float rstd = rsqrtf(var + BN_EPS);
    float sc = rstd * gamma[col];
    g_scale[col] = sc;
    g_shift[col] = beta[col] - mean * sc;
}

__global__ void foldw_kernel(const float* __restrict__ W_in) {
    int gid = blockIdx.x * 256 + threadIdx.x;
    if (gid >= NIN * 64) return;
    int c = gid >> 6;
    int j = gid & 63;
    int k = j >> 5, d = j & 31;
    float w = g_scale[c] * W_in[(size_t)k * NIN * D + c * D + d];
    __nv_bfloat16 h = __float2bfloat16(w);
    g_WpH[gid] = h;
    g_WpL[gid] = __float2bfloat16(w - __bfloat162float(h));
}

__global__ void foldb_kernel(const float* __restrict__ W_in,
                             const float* __restrict__ b_in) {
    __shared__ float red[1024];
    int j = blockIdx.x;
    int k = j >> 5, d = j & 31;
    float s = 0.f;
    for (int c = threadIdx.x; c < NIN; c += 1024)
        s += g_shift[c] * W_in[(size_t)k * NIN * D + c * D + d];
    red[threadIdx.x] = s;
    __syncthreads();
    for (int off = 512; off; off >>= 1) {
        if (threadIdx.x < off) red[threadIdx.x] += red[threadIdx.x + off];
        __syncthreads();
    }
    if (threadIdx.x == 0) g_bp[j] = b_in[j] + red[0];
}

// ---------------- input GEMM (tensor core, bf16 3-pass) ----------------
// relu(x @ W' + b'), M=8192 N=64 K=3072. tile 64x64, kt=64. grid 128, 256 thr.
// 8 warps: (w&3) -> m16 slice, (w>>2) -> n32 slice.
#define AST 72
__global__ void __launch_bounds__(256) gemm_in_tc(const float* __restrict__ x) {
    __shared__ __nv_bfloat16 Ah[64 * AST];
    __shared__ __nv_bfloat16 Al[64 * AST];
    __shared__ __nv_bfloat16 Bh[64 * AST];
    __shared__ __nv_bfloat16 Bl[64 * AST];
    int tid = threadIdx.x;
    int w = tid >> 5, l = tid & 31;
    int wm = w & 3, wn = w >> 2;
    int rowBase = blockIdx.x * 64;
    unsigned ah_b = smem_u32(Ah), al_b = smem_u32(Al);
    unsigned bh_b = smem_u32(Bh), bl_b = smem_u32(Bl);

    float c[4][4];
    #pragma unroll
    for (int i = 0; i < 4; i++)
        #pragma unroll
        for (int j = 0; j < 4; j++) c[i][j] = 0.f;

    int a_row = wm * 16 + (l & 7) + ((l >> 3) & 1) * 8;
    int a_kof = (l >> 4) * 8;
    int b_k = (l & 7) + ((l >> 3) & 1) * 8;
    int b_n = (l >> 4) * 8;

    for (int kb = 0; kb < NIN; kb += 64) {
        // stage A tile 64x64 f32 -> bf16 hi/lo (4 float4 per thread)
        #pragma unroll
        for (int p = 0; p < 4; p++) {
            int idx = p * 256 + tid;           // 0..1023
            int row = idx >> 4;
            int c4 = (idx & 15) * 4;
            float4 v = *(const float4*)&x[(size_t)(rowBase + row) * NIN + kb + c4];
            uint2 hv, lv;
            hv.x = pack_hi2(v.x, v.y); hv.y = pack_hi2(v.z, v.w);
            lv.x = pack_lo2(v.x, v.y); lv.y = pack_lo2(v.z, v.w);
            *(uint2*)&Ah[row * AST + c4] = hv;
            *(uint2*)&Al[row * AST + c4] = lv;
        }
        // stage B tile 64x64 bf16 hi/lo (2 uint4 per thread)
        #pragma unroll
        for (int p = 0; p < 2; p++) {
            int idx = p * 256 + tid;           // 0..511
            int k = idx >> 3;
            int n8 = (idx & 7) * 8;
            *(uint4*)&Bh[k * AST + n8] = *(const uint4*)&g_WpH[(kb + k) * 64 + n8];
            *(uint4*)&Bl[k * AST + n8] = *(const uint4*)&g_WpL[(kb + k) * 64 + n8];
        }
        __syncthreads();
        #pragma unroll
        for (int ks = 0; ks < 4; ks++) {
            int k0 = ks * 16;
            unsigned a_off = (unsigned)(a_row * (AST * 2) + (k0 + a_kof) * 2);
            unsigned ah[4], al[4];
            ldsm_x4(ah[0], ah[1], ah[2], ah[3], ah_b + a_off);
            ldsm_x4(al[0], al[1], al[2], al[3], al_b + a_off);
            #pragma unroll
            for (int g = 0; g < 2; g++) {
                int n0 = wn * 32 + g * 16;
                unsigned b_off = (unsigned)((k0 + b_k) * (AST * 2) + (n0 + b_n) * 2);
                unsigned h0, h1, h2, h3, q0, q1, q2, q3;
                ldsm_x4_t(h0, h1, h2, h3, bh_b + b_off);
                ldsm_x4_t(q0, q1, q2, q3, bl_b + b_off);
                mma_bf16(c[2 * g],     ah, h0, h1);
                mma_bf16(c[2 * g + 1], ah, h2, h3);
                mma_bf16(c[2 * g],     ah, q0, q1);
                mma_bf16(c[2 * g + 1], ah, q2, q3);
                mma_bf16(c[2 * g],     al, h0, h1);
                mma_bf16(c[2 * g + 1], al, h2, h3);
            }
        }
        __syncthreads();
    }
    // epilogue: + bias, relu, write g_in0/g_in1
    int r0 = rowBase + wm * 16 + (l >> 2);
    #pragma unroll
    for (int nb = 0; nb < 4; nb++) {
        int col = wn * 32 + nb * 8 + (l & 3) * 2;
        float2 bp = *(const float2*)&g_bp[col];
        float2 v0, v1;
        v0.x = fmaxf(c[nb][0] + bp.x, 0.f);
        v0.y = fmaxf(c[nb][1] + bp.y, 0.f);
        v1.x = fmaxf(c[nb][2] + bp.x, 0.f);
        v1.y = fmaxf(c[nb][3] + bp.y, 0.f);
        if (col < 32) {
            *(float2*)&g_in0[r0 * D + col] = v0;
            *(float2*)&g_in0[(r0 + 8) * D + col] = v1;
        } else {
            *(float2*)&g_in1[r0 * D + col - 32] = v0;
            *(float2*)&g_in1[(r0 + 8) * D + col - 32] = v1;
        }
    }
}

// ---------------- persistent bank-chain kernel ----------------
__device__ __forceinline__ void grid_bar() {
    __syncthreads();
    if (threadIdx.x == 0) {
        unsigned gen = *(volatile unsigned*)&g_barg;
        __threadfence();
        if (atomicAdd(&g_barc, 1u) == gridDim.x - 1) {
            atomicExch(&g_barc, 0u);
            __threadfence();
            *(volatile unsigned*)&g_barg = gen + 1;
        } else {
            while (*(volatile unsigned*)&g_barg == gen) { }
        }
        __threadfence();
    }
    __syncthreads();
}

__global__ void __launch_bounds__(256, 1) chain_kernel(
    const float* __restrict__ Wg, const float* __restrict__ Wd,
    const float* __restrict__ bd, float* __restrict__ tg) {
    __shared__ float actT[4][32][68];
    __shared__ float sWd[32 * 32];
    __shared__ float sbd[32];
    __shared__ float sWgv[32];
    __shared__ float sgate[64];
    __shared__ float stg[64];
    __shared__ float smean[16][32];
    __shared__ float srstd[16][32];
    __shared__ float red1[8][32];
    __shared__ float red2[8][32];
    __shared__ float sgb;

    int tid = threadIdx.x;
    int blk = blockIdx.x;
    int rowBase = blk * 64;
    int jx = tid & 15, ry = tid >> 4;
    int j0 = jx * 2, r0 = ry * 4;
    int warp = tid >> 5, lane = tid & 31;
    if (tid < 64) stg[tid] = 0.f;

    for (int t = 0; t < 16; t++) {
        float acc[4][2];
        if (t <= 1) {
            const float* src = (t == 0) ? g_in0 : g_in1;
            #pragma unroll
            for (int i = 0; i < 4; i++) {
                float2 v = *(const float2*)&src[(rowBase + r0 + i) * D + j0];
                acc[i][0] = v.x; acc[i][1] = v.y;
            }
        } else {
            #pragma unroll
            for (int i = 0; i < 4; i++) { acc[i][0] = 0.f; acc[i][1] = 0.f; }
        }
        int s0 = (t - 4 < 0) ? 0 : t - 4;
        int ecnt = (t < 4) ? t : 4;
        int ebase = (t <= 1) ? 0 : (t == 2) ? 1 : (t == 3) ? 3 : (t == 4) ? 6 : 10 + (t - 5) * 4;

        for (int ei = 0; ei < ecnt; ei++) {
            int e = ebase + ei, s = s0 + ei, slot = s & 3;
            #pragma unroll
            for (int p = 0; p < 4; p++) {
                int idx = p * 256 + tid;
                sWd[idx] = Wd[e * 1024 + idx] * srstd[s][idx >> 5];
            }
            if (tid < 32) sWgv[tid] = Wg[e * 32 + tid] * srstd[s][tid];
            __syncthreads();
            if (warp == 0) {
                float sum = 0.f;
                #pragma unroll
                for (int k = 0; k < 32; k++) sum += smean[s][k] * sWd[k * 32 + lane];
                sbd[lane] = bd[e * 32 + lane] - sum;
            } else if (warp == 1) {
                float v = smean[s][lane] * sWgv[lane];
                #pragma unroll
                for (int o = 16; o; o >>= 1) v += __shfl_xor_sync(~0u, v, o);
                if (lane == 0) sgb = -v;
            } else if (warp < 4) {
                int row = (warp - 2) * 32 + lane;
                float g = 0.f;
                #pragma unroll
                for (int k = 0; k < 32; k++) g += actT[slot][k][row] * sWgv[k];
                sgate[row] = g;
            }
            __syncthreads();
            float gb = sgb;
            float gi[4];
            #pragma unroll
            for (int i = 0; i < 4; i++)
                gi[i] = fminf(fmaxf(sgate[r0 + i] + gb, 0.f), 1.f);
            if (tid < 64) stg[tid] += fminf(fmaxf(sgate[tid] + gb, 0.f), 1.f);
            float dat[4][2];
            #pragma unroll
            for (int i = 0; i < 4; i++) { dat[i][0] = sbd[j0]; dat[i][1] = sbd[j0 + 1]; }
            #pragma unroll
            for (int k = 0; k < 32; k++) {
                float4 a4 = *(const float4*)&actT[slot][k][r0];
                float w0 = sWd[k * 32 + j0], w1 = sWd[k * 32 + j0 + 1];
                dat[0][0] += a4.x * w0; dat[0][1] += a4.x * w1;
                dat[1][0] += a4.y * w0; dat[1][1] += a4.y * w1;
                dat[2][0] += a4.z * w0; dat[2][1] += a4.z * w1;
                dat[3][0] += a4.w * w0; dat[3][1] += a4.w * w1;
            }
            #pragma unroll
            for (int i = 0; i < 4; i++) {
                acc[i][0] += gi[i] * dat[i][0];
                acc[i][1] += gi[i] * dat[i][1];
            }
            __syncthreads();
        }

        float v[4][2];
        #pragma unroll
        for (int i = 0; i < 4; i++) {
            v[i][0] = fmaxf(acc[i][0], 0.f);
            v[i][1] = fmaxf(acc[i][1], 0.f);
        }
        int slot_t = t & 3;
        #pragma unroll
        for (int cc = 0; cc < 2; cc++) {
            float4 st = make_float4(v[0][cc], v[1][cc], v[2][cc], v[3][cc]);
            *(float4*)&actT[slot_t][j0 + cc][r0] = st;
            if (t >= 14) {
                int krow = (t - 14) * 32 + j0 + cc;
                uint2 hv, lv;
                hv.x = pack_hi2(st.x, st.y); hv.y = pack_hi2(st.z, st.w);
                lv.x = pack_lo2(st.x, st.y); lv.y = pack_lo2(st.z, st.w);
                *(uint2*)&g_preTH[krow * BATCH + rowBase + r0] = hv;
                *(uint2*)&g_preTL[krow * BATCH + rowBase + r0] = lv;
            }
        }
        __syncthreads();
        {
            float s1 = 0.f, s2 = 0.f;
            #pragma unroll
            for (int q = 0; q < 8; q++) {
                float xv = actT[slot_t][lane][warp * 8 + q];
                s1 += xv; s2 += xv * xv;
            }
            red1[warp][lane] = s1;
            red2[warp][lane] = s2;
        }
        __syncthreads();
        if (warp == 0) {
            float s1 = 0.f, s2 = 0.f;
            #pragma unroll
            for (int g2 = 0; g2 < 8; g2++) { s1 += red1[g2][lane]; s2 += red2[g2][lane]; }
            g_p1s[(t * CB + blk) * 32 + lane] = s1;
            g_p2s[(t * CB + blk) * 32 + lane] = s2;
        }
        __threadfence();
        grid_bar();
        if (warp < 4) {
            float s1 = 0.f, s2 = 0.f;
            #pragma unroll 8
            for (int b = warp; b < CB; b += 4) {
                s1 += __ldcg(&g_p1s[(t * CB + b) * 32 + lane]);
                s2 += __ldcg(&g_p2s[(t * CB + b) * 32 + lane]);
            }
            red1[warp][lane] = s1;
            red2[warp][lane] = s2;
        }
        __syncthreads();
        if (warp == 0) {
            float s1 = red1[0][lane] + red1[1][lane] + red1[2][lane] + red1[3][lane];
            float s2 = red2[0][lane] + red2[1][lane] + red2[2][lane] + red2[3][lane];
            float mean = s1 * (1.f / BATCH);
            float var = s2 * (1.f / BATCH) - mean * mean;
            float rs = rsqrtf(var + BN_EPS);
            smean[t][lane] = mean;
            srstd[t][lane] = rs;
            if (blk == 0) { g_mean[t * 32 + lane] = mean; g_rstd[t * 32 + lane] = rs; }
        }
        __syncthreads();
    }
    if (tid < 64) tg[rowBase + tid] = stg[tid];
}

// ---------------- fold BN of banks 14/15 into Wout ----------------
__global__ void woutfold_kernel(const float* __restrict__ Wout) {
    int n = blockIdx.x * 256 + threadIdx.x;   // 0..1023
    float bias = 0.f;
    #pragma unroll 8
    for (int k = 0; k < 64; k++) {
        int bank = k >> 5, d = k & 31;
        float w = (n < NOUT) ? Wout[(size_t)bank * D * NOUT + d * NOUT + n] : 0.f;
        float rs = g_rstd[(14 + bank) * 32 + d];
        float mn = g_mean[(14 + bank) * 32 + d];
        float wp = w * rs;
        bias -= mn * wp;
        __nv_bfloat16 h = __float2bfloat16(wp);
        g_WoutH[k * 1024 + n] = h;
        g_WoutL[k * 1024 + n] = __float2bfloat16(wp - __bfloat162float(h));
    }
    g_bout[n] = bias;
}

// ---------------- output GEMM (tensor core) ----------------
// out = preT @ Wout' + bias. M=8192 N=1000(1024) K=64. tile 64x64.
// grid (128, 16). 8 warps: (w&3)->m16, (w>>2)->n32.
#define ATM 72
__global__ void __launch_bounds__(256) gemm_out_tc(float* __restrict__ out) {
    __shared__ __nv_bfloat16 ATh[64 * ATM];   // [k][m]
    __shared__ __nv_bfloat16 ATl[64 * ATM];
    __shared__ __nv_bfloat16 Bh[64 * AST];    // [k][n]
    __shared__ __nv_bfloat16 Bl[64 * AST];
    int tid = threadIdx.x;
    int w = tid >> 5, l = tid & 31;
    int wm = w & 3, wn = w >> 2;
    int rowBase = blockIdx.x * 64;
    int colBase = blockIdx.y * 64;
    unsigned ah_b = smem_u32(ATh), al_b = smem_u32(ATl);
    unsigned bh_b = smem_u32(Bh), bl_b = smem_u32(Bl);

    #pragma unroll
    for (int p = 0; p < 2; p++) {
        int idx = p * 256 + tid;      // 0..511
        int k = idx >> 3;
        int m8 = (idx & 7) * 8;
        *(uint4*)&ATh[k * ATM + m8] = *(const uint4*)&g_preTH[k * BATCH + rowBase + m8];
        *(uint4*)&ATl[k * ATM + m8] = *(const uint4*)&g_preTL[k * BATCH + rowBase + m8];
    }
    #pragma unroll
    for (int p = 0; p < 2; p++) {
        int idx = p * 256 + tid;      // 0..511
        int k = idx >> 3;
        int n8 = (idx & 7) * 8;
        *(uint4*)&Bh[k * AST + n8] = *(const uint4*)&g_WoutH[k * 1024 + colBase + n8];
        *(uint4*)&Bl[k * AST + n8] = *(const uint4*)&g_WoutL[k * 1024 + colBase + n8];
    }
    __syncthreads();

    float c[4][4];
    #pragma unroll
    for (int i = 0; i < 4; i++)
        #pragma unroll
        for (int j = 0; j < 4; j++) c[i][j] = 0.f;

    int a_k = (l & 7) + (l >> 4) * 8;
    int a_m = wm * 16 + ((l >> 3) & 1) * 8;
    int b_k = (l & 7) + ((l >> 3) & 1) * 8;
    int b_n = (l >> 4) * 8;

    #pragma unroll
    for (int ks = 0; ks < 4; ks++) {
        int k0 = ks * 16;
        unsigned a_off = (unsigned)((k0 + a_k) * (ATM * 2) + a_m * 2);
        unsigned ah[4], al[4];
        ldsm_x4_t(ah[0], ah[1], ah[2], ah[3], ah_b + a_off);
        ldsm_x4_t(al[0], al[1], al[2], al[3], al_b + a_off);
        #pragma unroll
        for (int g = 0; g < 2; g++) {
            int n0 = wn * 32 + g * 16;
            unsigned b_off = (unsigned)((k0 + b_k) * (AST * 2) + (n0 + b_n) * 2);
            unsigned h0, h1, h2, h3, q0, q1, q2, q3;
            ldsm_x4_t(h0, h1, h2, h3, bh_b + b_off);
            ldsm_x4_t(q0, q1, q2, q3, bl_b + b_off);
            mma_bf16(c[2 * g],     ah, h0, h1);
            mma_bf16(c[2 * g + 1], ah, h2, h3);
            mma_bf16(c[2 * g],     ah, q0, q1);
            mma_bf16(c[2 * g + 1], ah, q2, q3);
            mma_bf16(c[2 * g],     al, h0, h1);
            mma_bf16(c[2 * g + 1], al, h2, h3);
        }
    }
    int r0 = rowBase + wm * 16 + (l >> 2);
    #pragma unroll
    for (int nb = 0; nb < 4; nb++) {
        int col = colBase + wn * 32 + nb * 8 + (l & 3) * 2;
        if (col < NOUT) {
            float2 bo = *(const float2*)&g_bout[col];
            float2 v0 = make_float2(c[nb][0] + bo.x, c[nb][1] + bo.y);
            float2 v1 = make_float2(c[nb][2] + bo.x, c[nb][3] + bo.y);
            *(float2*)&out[(size_t)r0 * NOUT + col] = v0;
            *(float2*)&out[(size_t)(r0 + 8) * NOUT + col] = v1;
        }
    }
}

// ---------------- launch ----------------
extern "C" void kernel_launch(void* const* d_in, const int* in_sizes, int n_in,
                              void* d_out, int out_size) {
    const float* x     = (const float*)d_in[0];
    const float* gamma = (const float*)d_in[1];
    const float* beta  = (const float*)d_in[2];
    const float* W_in  = (const float*)d_in[3];
    const float* b_in  = (const float*)d_in[4];
    const float* Wg    = (const float*)d_in[5];
    const float* Wd    = (const float*)d_in[6];
    const float* bd    = (const float*)d_in[7];
    const float* Wout  = (const float*)d_in[8];
    float* out = (float*)d_out;

    float* tg;
    if (out_size >= BATCH * NOUT + BATCH) {
        tg = out + (size_t)BATCH * NOUT;
    } else {
        void* p = nullptr;
        cudaGetSymbolAddress(&p, g_tg_fallback);
        tg = (float*)p;
    }

    xstats_partial_kernel<<<dim3(12, 64), 256>>>(x);
    xfinal_kernel<<<12, 256>>>(gamma, beta);
    foldw_kernel<<<768, 256>>>(W_in);
    foldb_kernel<<<64, 1024>>>(W_in, b_in);
    gemm_in_tc<<<128, 256>>>(x);
    chain_kernel<<<CB, 256>>>(Wg, Wd, bd, tg);
    woutfold_kernel<<<4, 256>>>(Wout);
    gemm_out_tc<<<dim3(128, 16), 256>>>(out);
}

// round 6
// speedup vs baseline: 3.7997x; 1.2449x over previous
#include <cuda_runtime.h>
#include <cuda_bf16.h>
#include <stdint.h>
#include <math.h>

#define NBANKS 16
#define D 32
#define NIN 3072
#define NOUT 1000
#define BATCH 8192
#define BN_EPS 1e-5f
#define CB 128

// ---------------- device scratch ----------------
__device__ float g_px1[64 * NIN];
__device__ float g_px2[64 * NIN];
__device__ float g_scale[NIN];
__device__ float g_shift[NIN];
__device__ __nv_bfloat16 g_WpH[NIN * 64];   // folded input weights hi
__device__ __nv_bfloat16 g_WpL[NIN * 64];   // folded input weights lo
__device__ float g_bp[64];
__device__ float g_in0[BATCH * D];
__device__ float g_in1[BATCH * D];
__device__ __nv_bfloat16 g_preTH[64 * BATCH];  // banks14,15 NORMALIZED acts, [k][row]
__device__ __nv_bfloat16 g_preTL[64 * BATCH];
__device__ __nv_bfloat16 g_WoutH[64 * 1024];   // Wout split, [k][n] pad 1024
__device__ __nv_bfloat16 g_WoutL[64 * 1024];
__device__ float g_p1s[NBANKS * CB * 32];
__device__ float g_p2s[NBANKS * CB * 32];
__device__ unsigned g_barc;
__device__ unsigned g_barg;
__device__ float g_tg_fallback[BATCH];

// ---------------- helpers ----------------
__device__ __forceinline__ unsigned smem_u32(const void* p) {
    return (unsigned)__cvta_generic_to_shared(p);
}
__device__ __forceinline__ void ldsm_x4(unsigned& r0, unsigned& r1, unsigned& r2,
                                        unsigned& r3, unsigned addr) {
    asm volatile("ldmatrix.sync.aligned.m8n8.x4.shared.b16 {%0,%1,%2,%3},[%4];"
                 : "=r"(r0), "=r"(r1), "=r"(r2), "=r"(r3) : "r"(addr));
}
__device__ __forceinline__ void ldsm_x4_t(unsigned& r0, unsigned& r1, unsigned& r2,
                                          unsigned& r3, unsigned addr) {
    asm volatile("ldmatrix.sync.aligned.m8n8.x4.trans.shared.b16 {%0,%1,%2,%3},[%4];"
                 : "=r"(r0), "=r"(r1), "=r"(r2), "=r"(r3) : "r"(addr));
}
__device__ __forceinline__ void mma_bf16(float* c, const unsigned* a,
                                         unsigned b0, unsigned b1) {
    asm volatile(
        "mma.sync.aligned.m16n8k16.row.col.f32.bf16.bf16.f32 "
        "{%0,%1,%2,%3},{%4,%5,%6,%7},{%8,%9},{%0,%1,%2,%3};"
        : "+f"(c[0]), "+f"(c[1]), "+f"(c[2]), "+f"(c[3])
        : "r"(a[0]), "r"(a[1]), "r"(a[2]), "r"(a[3]), "r"(b0), "r"(b1));
}
__device__ __forceinline__ unsigned pack_hi2(float x, float y) {
    __nv_bfloat16 hx = __float2bfloat16(x), hy = __float2bfloat16(y);
    return ((unsigned)__bfloat16_as_ushort(hy) << 16) | __bfloat16_as_ushort(hx);
}
__device__ __forceinline__ unsigned pack_lo2(float x, float y) {
    __nv_bfloat16 hx = __float2bfloat16(x), hy = __float2bfloat16(y);
    float lx = x - __bfloat162float(hx), ly = y - __bfloat162float(hy);
    __nv_bfloat16 bx = __float2bfloat16(lx), by = __float2bfloat16(ly);
    return ((unsigned)__bfloat16_as_ushort(by) << 16) | __bfloat16_as_ushort(bx);
}

// ---------------- x stats + folds ----------------
__global__ void xstats_partial_kernel(const float* __restrict__ x) {
    int col = blockIdx.x * 256 + threadIdx.x;
    int chunk = blockIdx.y;
    float s1 = 0.f, s2 = 0.f;
    int r0 = chunk * 128;
    #pragma unroll 4
    for (int r = r0; r < r0 + 128; r++) {
        float v = x[(size_t)r * NIN + col];
        s1 += v; s2 += v * v;
    }
    g_px1[chunk * NIN + col] = s1;
    g_px2[chunk * NIN + col] = s2;
}

__global__ void xfinal_kernel(const float* __restrict__ gamma,
                              const float* __restrict__ beta) {
    int col = blockIdx.x * 256 + threadIdx.x;
    float s1 = 0.f, s2 = 0.f;
    #pragma unroll 8
    for (int c = 0; c < 64; c++) { s1 += g_px1[c * NIN + col]; s2 += g_px2[c * NIN + col]; }
    float mean = s1 * (1.f / BATCH);
    float var = s2 * (1.f / BATCH) - mean * mean;
    float rstd = rsqrtf(var + BN_EPS);
    float sc = rstd * gamma[col];
    g_scale[col] = sc;
    g_shift[col] = beta[col] - mean * sc;
}

__global__ void foldw_kernel(const float* __restrict__ W_in) {
    int gid = blockIdx.x * 256 + threadIdx.x;
    if (gid >= NIN * 64) return;
    int c = gid >> 6;
    int j = gid & 63;
    int k = j >> 5, d = j & 31;
    float w = g_scale[c] * W_in[(size_t)k * NIN * D + c * D + d];
    __nv_bfloat16 h = __float2bfloat16(w);
    g_WpH[gid] = h;
    g_WpL[gid] = __float2bfloat16(w - __bfloat162float(h));
}

// coalesced: grid 2 (k), 1024 threads; warp = c-chunk, lane = d.
__global__ void foldb_kernel(const float* __restrict__ W_in,
                             const float* __restrict__ b_in) {
    __shared__ float red[32][32];
    int k = blockIdx.x;
    int warp = threadIdx.x >> 5, lane = threadIdx.x & 31;
    float s = 0.f;
    int c0 = warp * 96;
    #pragma unroll 4
    for (int c = c0; c < c0 + 96; c++)
        s += g_shift[c] * W_in[(size_t)k * NIN * D + c * D + lane];
    red[warp][lane] = s;
    __syncthreads();
    if (warp == 0) {
        float t = 0.f;
        #pragma unroll
        for (int w2 = 0; w2 < 32; w2++) t += red[w2][lane];
        g_bp[k * 32 + lane] = b_in[k * 32 + lane] + t;
    }
}

// Wout split (no BN fold — acts are pre-normalized). grid 4 x 256.
__global__ void woutfold_kernel(const float* __restrict__ Wout) {
    int n = blockIdx.x * 256 + threadIdx.x;   // 0..1023
    #pragma unroll 8
    for (int k = 0; k < 64; k++) {
        int bank = k >> 5, d = k & 31;
        float w = (n < NOUT) ? Wout[(size_t)bank * D * NOUT + d * NOUT + n] : 0.f;
        __nv_bfloat16 h = __float2bfloat16(w);
        g_WoutH[k * 1024 + n] = h;
        g_WoutL[k * 1024 + n] = __float2bfloat16(w - __bfloat162float(h));
    }
}

// ---------------- input GEMM (tensor core, bf16 3-pass, double-buffered) ----
// relu(x @ W' + b'), M=8192 N=64 K=3072. tile 64 rows x 32 k. grid 128, 256.
// APAD stride must be a multiple of 8 bf16 (16 bytes) for ldmatrix row alignment.
#define APAD 40
#define BPAD 72
__global__ void __launch_bounds__(256) gemm_in_tc(const float* __restrict__ x) {
    __shared__ __nv_bfloat16 Ah[2][64 * APAD];
    __shared__ __nv_bfloat16 Al[2][64 * APAD];
    __shared__ __nv_bfloat16 Bh[2][32 * BPAD];
    __shared__ __nv_bfloat16 Bl[2][32 * BPAD];
    int tid = threadIdx.x;
    int w = tid >> 5, l = tid & 31;
    int wm = w & 3, wn = w >> 2;
    int rowBase = blockIdx.x * 64;

    // per-thread staging coords
    int a_r0 = tid >> 3;            // rows (tid>>3) and +32
    int a_k4 = (tid & 7) * 4;
    int b_kk = tid >> 3;
    int b_n8 = (tid & 7) * 8;

    float4 pa0, pa1;
    uint4 pbh, pbl;
    // preload tile 0
    pa0 = *(const float4*)&x[(size_t)(rowBase + a_r0) * NIN + a_k4];
    pa1 = *(const float4*)&x[(size_t)(rowBase + a_r0 + 32) * NIN + a_k4];
    pbh = *(const uint4*)&g_WpH[b_kk * 64 + b_n8];
    pbl = *(const uint4*)&g_WpL[b_kk * 64 + b_n8];
    {
        uint2 h0, l0;
        h0.x = pack_hi2(pa0.x, pa0.y); h0.y = pack_hi2(pa0.z, pa0.w);
        l0.x = pack_lo2(pa0.x, pa0.y); l0.y = pack_lo2(pa0.z, pa0.w);
        *(uint2*)&Ah[0][a_r0 * APAD + a_k4] = h0;
        *(uint2*)&Al[0][a_r0 * APAD + a_k4] = l0;
        h0.x = pack_hi2(pa1.x, pa1.y); h0.y = pack_hi2(pa1.z, pa1.w);
        l0.x = pack_lo2(pa1.x, pa1.y); l0.y = pack_lo2(pa1.z, pa1.w);
        *(uint2*)&Ah[0][(a_r0 + 32) * APAD + a_k4] = h0;
        *(uint2*)&Al[0][(a_r0 + 32) * APAD + a_k4] = l0;
        *(uint4*)&Bh[0][b_kk * BPAD + b_n8] = pbh;
        *(uint4*)&Bl[0][b_kk * BPAD + b_n8] = pbl;
    }
    __syncthreads();

    float c[4][4];
    #pragma unroll
    for (int i = 0; i < 4; i++)
        #pragma unroll
        for (int j = 0; j < 4; j++) c[i][j] = 0.f;

    int a_row = wm * 16 + (l & 7) + ((l >> 3) & 1) * 8;
    int a_kof = (l >> 4) * 8;
    int b_k = (l & 7) + ((l >> 3) & 1) * 8;
    int b_n = (l >> 4) * 8;

    for (int kt = 0; kt < 96; kt++) {
        int cur = kt & 1, nxt = cur ^ 1;
        if (kt < 95) {
            int kb = (kt + 1) * 32;
            pa0 = *(const float4*)&x[(size_t)(rowBase + a_r0) * NIN + kb + a_k4];
            pa1 = *(const float4*)&x[(size_t)(rowBase + a_r0 + 32) * NIN + kb + a_k4];
            pbh = *(const uint4*)&g_WpH[(kb + b_kk) * 64 + b_n8];
            pbl = *(const uint4*)&g_WpL[(kb + b_kk) * 64 + b_n8];
        }
        unsigned ahb = smem_u32(Ah[cur]), alb = smem_u32(Al[cur]);
        unsigned bhb = smem_u32(Bh[cur]), blb = smem_u32(Bl[cur]);
        #pragma unroll
        for (int ks = 0; ks < 2; ks++) {
            int k0 = ks * 16;
            unsigned a_off = (unsigned)(a_row * (APAD * 2) + (k0 + a_kof) * 2);
            unsigned ah[4], al[4];
            ldsm_x4(ah[0], ah[1], ah[2], ah[3], ahb + a_off);
            ldsm_x4(al[0], al[1], al[2], al[3], alb + a_off);
            #pragma unroll
            for (int g = 0; g < 2; g++) {
                int n0 = wn * 32 + g * 16;
                unsigned b_off = (unsigned)((k0 + b_k) * (BPAD * 2) + (n0 + b_n) * 2);
                unsigned h0, h1, h2, h3, q0, q1, q2, q3;
                ldsm_x4_t(h0, h1, h2, h3, bhb + b_off);
                ldsm_x4_t(q0, q1, q2, q3, blb + b_off);
                mma_bf16(c[2 * g],     ah, h0, h1);
                mma_bf16(c[2 * g + 1], ah, h2, h3);
                mma_bf16(c[2 * g],     ah, q0, q1);
                mma_bf16(c[2 * g + 1], ah, q2, q3);
                mma_bf16(c[2 * g],     al, h0, h1);
                mma_bf16(c[2 * g + 1], al, h2, h3);
            }
        }
        if (kt < 95) {
            uint2 h0, l0;
            h0.x = pack_hi2(pa0.x, pa0.y); h0.y = pack_hi2(pa0.z, pa0.w);
            l0.x = pack_lo2(pa0.x, pa0.y); l0.y = pack_lo2(pa0.z, pa0.w);
            *(uint2*)&Ah[nxt][a_r0 * APAD + a_k4] = h0;
            *(uint2*)&Al[nxt][a_r0 * APAD + a_k4] = l0;
            h0.x = pack_hi2(pa1.x, pa1.y); h0.y = pack_hi2(pa1.z, pa1.w);
            l0.x = pack_lo2(pa1.x, pa1.y); l0.y = pack_lo2(pa1.z, pa1.w);
            *(uint2*)&Ah[nxt][(a_r0 + 32) * APAD + a_k4] = h0;
            *(uint2*)&Al[nxt][(a_r0 + 32) * APAD + a_k4] = l0;
            *(uint4*)&Bh[nxt][b_kk * BPAD + b_n8] = pbh;
            *(uint4*)&Bl[nxt][b_kk * BPAD + b_n8] = pbl;
        }
        __syncthreads();
    }
    // epilogue: + bias, relu
    int r0 = rowBase + wm * 16 + (l >> 2);
    #pragma unroll
    for (int nb = 0; nb < 4; nb++) {
        int col = wn * 32 + nb * 8 + (l & 3) * 2;
        float2 bp = *(const float2*)&g_bp[col];
        float2 v0, v1;
        v0.x = fmaxf(c[nb][0] + bp.x, 0.f);
        v0.y = fmaxf(c[nb][1] + bp.y, 0.f);
        v1.x = fmaxf(c[nb][2] + bp.x, 0.f);
        v1.y = fmaxf(c[nb][3] + bp.y, 0.f);
        if (col < 32) {
            *(float2*)&g_in0[r0 * D + col] = v0;
            *(float2*)&g_in0[(r0 + 8) * D + col] = v1;
        } else {
            *(float2*)&g_in1[r0 * D + col - 32] = v0;
            *(float2*)&g_in1[(r0 + 8) * D + col - 32] = v1;
        }
    }
}

// ---------------- persistent bank-chain kernel (normalize-in-place) --------
__device__ __forceinline__ void grid_bar() {
    __syncthreads();
    if (threadIdx.x == 0) {
        unsigned gen = *(volatile unsigned*)&g_barg;
        __threadfence();
        if (atomicAdd(&g_barc, 1u) == gridDim.x - 1) {
            atomicExch(&g_barc, 0u);
            __threadfence();
            *(volatile unsigned*)&g_barg = gen + 1;
        } else {
            while (*(volatile unsigned*)&g_barg == gen) { }
        }
        __threadfence();
    }
    __syncthreads();
}

__global__ void __launch_bounds__(256, 1) chain_kernel(
    const float* __restrict__ Wg, const float* __restrict__ Wd,
    const float* __restrict__ bd, float* __restrict__ tg) {
    __shared__ __align__(16) float actT[4][32][68];   // NORMALIZED acts window
    __shared__ float sgraw[4][64];
    __shared__ float stg[64];
    __shared__ float smean[4][32], srstd[4][32];
    __shared__ float red1[8][32], red2[8][32];

    int tid = threadIdx.x;
    int blk = blockIdx.x;
    int rowBase = blk * 64;
    int j0 = (tid & 15) * 2, r0 = (tid >> 4) * 4;
    int warp = tid >> 5, lane = tid & 31;
    int grow = tid & 63, gei = tid >> 6;
    int nd = tid >> 3, nrg = (tid & 7) * 8;   // normalize mapping
    if (tid < 64) stg[tid] = 0.f;

    for (int t = 0; t < 16; t++) {
        int s0 = (t - 4 < 0) ? 0 : t - 4;
        int ecnt = (t < 4) ? t : 4;
        int ebase = (t <= 1) ? 0 : (t == 2) ? 1 : (t == 3) ? 3 : (t == 4) ? 6 : 10 + (t - 5) * 4;

        // --- gate stage: all warps; thread -> (row, edge) ---
        if (ecnt > 0) {
            if (gei < ecnt) {
                int e = ebase + gei, slot = (s0 + gei) & 3;
                const float* wgp = Wg + e * 32;
                float g = 0.f;
                #pragma unroll
                for (int k = 0; k < 32; k++)
                    g += actT[slot][k][grow] * __ldg(&wgp[k]);
                sgraw[gei][grow] = g;
            }
            __syncthreads();
        }

        // --- gated accumulate: per thread 4 rows x 2 cols ---
        float acc[4][2];
        if (t <= 1) {
            const float* src = (t == 0) ? g_in0 : g_in1;
            #pragma unroll
            for (int i = 0; i < 4; i++) {
                float2 v = *(const float2*)&src[(rowBase + r0 + i) * D + j0];
                acc[i][0] = v.x; acc[i][1] = v.y;
            }
        } else {
            #pragma unroll
            for (int i = 0; i < 4; i++) { acc[i][0] = 0.f; acc[i][1] = 0.f; }
        }
        for (int ei = 0; ei < ecnt; ei++) {
            int e = ebase + ei, slot = (s0 + ei) & 3;
            float gi[4];
            #pragma unroll
            for (int i = 0; i < 4; i++)
                gi[i] = fminf(fmaxf(sgraw[ei][r0 + i], 0.f), 1.f);
            if ((tid & 15) == 0) {
                #pragma unroll
                for (int i = 0; i < 4; i++) stg[r0 + i] += gi[i];
            }
            float2 b2 = __ldg((const float2*)&bd[e * 32 + j0]);
            float dat[4][2];
            #pragma unroll
            for (int i = 0; i < 4; i++) { dat[i][0] = b2.x; dat[i][1] = b2.y; }
            const float* wp = Wd + e * 1024 + j0;
            #pragma unroll
            for (int k = 0; k < 32; k++) {
                float4 a4 = *(const float4*)&actT[slot][k][r0];
                float2 w2 = __ldg((const float2*)&wp[k * 32]);
                dat[0][0] += a4.x * w2.x; dat[0][1] += a4.x * w2.y;
                dat[1][0] += a4.y * w2.x; dat[1][1] += a4.y * w2.y;
                dat[2][0] += a4.z * w2.x; dat[2][1] += a4.z * w2.y;
                dat[3][0] += a4.w * w2.x; dat[3][1] += a4.w * w2.y;
            }
            #pragma unroll
            for (int i = 0; i < 4; i++) {
                acc[i][0] += gi[i] * dat[i][0];
                acc[i][1] += gi[i] * dat[i][1];
            }
        }

        // --- relu + store raw (transposed) ---
        int slot_t = t & 3;
        #pragma unroll
        for (int cc = 0; cc < 2; cc++) {
            float4 st = make_float4(fmaxf(acc[0][cc], 0.f), fmaxf(acc[1][cc], 0.f),
                                    fmaxf(acc[2][cc], 0.f), fmaxf(acc[3][cc], 0.f));
            *(float4*)&actT[slot_t][j0 + cc][r0] = st;
        }
        __syncthreads();

        // --- per-block column-stat partials ---
        {
            float s1 = 0.f, s2 = 0.f;
            #pragma unroll
            for (int q = 0; q < 8; q++) {
                float xv = actT[slot_t][lane][warp * 8 + q];
                s1 += xv; s2 += xv * xv;
            }
            red1[warp][lane] = s1;
            red2[warp][lane] = s2;
        }
        __syncthreads();
        if (warp == 0) {
            float s1 = 0.f, s2 = 0.f;
            #pragma unroll
            for (int g2 = 0; g2 < 8; g2++) { s1 += red1[g2][lane]; s2 += red2[g2][lane]; }
            g_p1s[(t * CB + blk) * 32 + lane] = s1;
            g_p2s[(t * CB + blk) * 32 + lane] = s2;
        }
        grid_bar();
        // --- finalize stats (redundant per block) ---
        {
            float s1 = 0.f, s2 = 0.f;
            #pragma unroll 4
            for (int b = warp; b < CB; b += 8) {
                s1 += __ldcg(&g_p1s[(t * CB + b) * 32 + lane]);
                s2 += __ldcg(&g_p2s[(t * CB + b) * 32 + lane]);
            }
            red1[warp][lane] = s1;
            red2[warp][lane] = s2;
        }
        __syncthreads();
        if (warp == 0) {
            float s1 = 0.f, s2 = 0.f;
            #pragma unroll
            for (int g2 = 0; g2 < 8; g2++) { s1 += red1[g2][lane]; s2 += red2[g2][lane]; }
            float mean = s1 * (1.f / BATCH);
            float var = s2 * (1.f / BATCH) - mean * mean;
            smean[slot_t][lane] = mean;
            srstd[slot_t][lane] = rsqrtf(var + BN_EPS);
        }
        __syncthreads();
        // --- normalize in place (+ export bf16 split for banks 14/15) ---
        {
            float m = smean[slot_t][nd], r = srstd[slot_t][nd];
            #pragma unroll
            for (int q2 = 0; q2 < 2; q2++) {
                float4 vv = *(float4*)&actT[slot_t][nd][nrg + q2 * 4];
                vv.x = (vv.x - m) * r; vv.y = (vv.y - m) * r;
                vv.z = (vv.z - m) * r; vv.w = (vv.w - m) * r;
                *(float4*)&actT[slot_t][nd][nrg + q2 * 4] = vv;
                if (t >= 14) {
                    int krow = (t - 14) * 32 + nd;
                    uint2 hv, lv;
                    hv.x = pack_hi2(vv.x, vv.y); hv.y = pack_hi2(vv.z, vv.w);
                    lv.x = pack_lo2(vv.x, vv.y); lv.y = pack_lo2(vv.z, vv.w);
                    *(uint2*)&g_preTH[krow * BATCH + rowBase + nrg + q2 * 4] = hv;
                    *(uint2*)&g_preTL[krow * BATCH + rowBase + nrg + q2 * 4] = lv;
                }
            }
        }
        __syncthreads();
    }
    if (tid < 64) tg[rowBase + tid] = stg[tid];
}

// ---------------- output GEMM (tensor core, no bias) ----------------
// out = A_norm @ WoutSplit. M=8192 N=1000(1024) K=64. tile 64x64. grid (128,16).
#define ATM 72
#define AST 72
__global__ void __launch_bounds__(256) gemm_out_tc(float* __restrict__ out) {
    __shared__ __nv_bfloat16 ATh[64 * ATM];   // [k][m]
    __shared__ __nv_bfloat16 ATl[64 * ATM];
    __shared__ __nv_bfloat16 Bh[64 * AST];    // [k][n]
    __shared__ __nv_bfloat16 Bl[64 * AST];
    int tid = threadIdx.x;
    int w = tid >> 5, l = tid & 31;
    int wm = w & 3, wn = w >> 2;
    int rowBase = blockIdx.x * 64;
    int colBase = blockIdx.y * 64;
    unsigned ah_b = smem_u32(ATh), al_b = smem_u32(ATl);
    unsigned bh_b = smem_u32(Bh), bl_b = smem_u32(Bl);

    #pragma unroll
    for (int p = 0; p < 2; p++) {
        int idx = p * 256 + tid;
        int k = idx >> 3;
        int m8 = (idx & 7) * 8;
        *(uint4*)&ATh[k * ATM + m8] = *(const uint4*)&g_preTH[k * BATCH + rowBase + m8];
        *(uint4*)&ATl[k * ATM + m8] = *(const uint4*)&g_preTL[k * BATCH + rowBase + m8];
    }
    #pragma unroll
    for (int p = 0; p < 2; p++) {
        int idx = p * 256 + tid;
        int k = idx >> 3;
        int n8 = (idx & 7) * 8;
        *(uint4*)&Bh[k * AST + n8] = *(const uint4*)&g_WoutH[k * 1024 + colBase + n8];
        *(uint4*)&Bl[k * AST + n8] = *(const uint4*)&g_WoutL[k * 1024 + colBase + n8];
    }
    __syncthreads();

    float c[4][4];
    #pragma unroll
    for (int i = 0; i < 4; i++)
        #pragma unroll
        for (int j = 0; j < 4; j++) c[i][j] = 0.f;

    int a_k = (l & 7) + (l >> 4) * 8;
    int a_m = wm * 16 + ((l >> 3) & 1) * 8;
    int b_k = (l & 7) + ((l >> 3) & 1) * 8;
    int b_n = (l >> 4) * 8;

    #pragma unroll
    for (int ks = 0; ks < 4; ks++) {
        int k0 = ks * 16;
        unsigned a_off = (unsigned)((k0 + a_k) * (ATM * 2) + a_m * 2);
        unsigned ah[4], al[4];
        ldsm_x4_t(ah[0], ah[1], ah[2], ah[3], ah_b + a_off);
        ldsm_x4_t(al[0], al[1], al[2], al[3], al_b + a_off);
        #pragma unroll
        for (int g = 0; g < 2; g++) {
            int n0 = wn * 32 + g * 16;
            unsigned b_off = (unsigned)((k0 + b_k) * (AST * 2) + (n0 + b_n) * 2);
            unsigned h0, h1, h2, h3, q0, q1, q2, q3;
            ldsm_x4_t(h0, h1, h2, h3, bh_b + b_off);
            ldsm_x4_t(q0, q1, q2, q3, bl_b + b_off);
            mma_bf16(c[2 * g],     ah, h0, h1);
            mma_bf16(c[2 * g + 1], ah, h2, h3);
            mma_bf16(c[2 * g],     ah, q0, q1);
            mma_bf16(c[2 * g + 1], ah, q2, q3);
            mma_bf16(c[2 * g],     al, h0, h1);
            mma_bf16(c[2 * g + 1], al, h2, h3);
        }
    }
    int r0 = rowBase + wm * 16 + (l >> 2);
    #pragma unroll
    for (int nb = 0; nb < 4; nb++) {
        int col = colBase + wn * 32 + nb * 8 + (l & 3) * 2;
        if (col < NOUT) {
            float2 v0 = make_float2(c[nb][0], c[nb][1]);
            float2 v1 = make_float2(c[nb][2], c[nb][3]);
            *(float2*)&out[(size_t)r0 * NOUT + col] = v0;
            *(float2*)&out[(size_t)(r0 + 8) * NOUT + col] = v1;
        }
    }
}

// ---------------- launch ----------------
extern "C" void kernel_launch(void* const* d_in, const int* in_sizes, int n_in,
                              void* d_out, int out_size) {
    const float* x     = (const float*)d_in[0];
    const float* gamma = (const float*)d_in[1];
    const float* beta  = (const float*)d_in[2];
    const float* W_in  = (const float*)d_in[3];
    const float* b_in  = (const float*)d_in[4];
    const float* Wg    = (const float*)d_in[5];
    const float* Wd    = (const float*)d_in[6];
    const float* bd    = (const float*)d_in[7];
    const float* Wout  = (const float*)d_in[8];
    float* out = (float*)d_out;

    float* tg;
    if (out_size >= BATCH * NOUT + BATCH) {
        tg = out + (size_t)BATCH * NOUT;
    } else {
        void* p = nullptr;
        cudaGetSymbolAddress(&p, g_tg_fallback);
        tg = (float*)p;
    }

    xstats_partial_kernel<<<dim3(12, 64), 256>>>(x);
    xfinal_kernel<<<12, 256>>>(gamma, beta);
    foldw_kernel<<<768, 256>>>(W_in);
    foldb_kernel<<<2, 1024>>>(W_in, b_in);
    woutfold_kernel<<<4, 256>>>(Wout);
    gemm_in_tc<<<128, 256>>>(x);
    chain_kernel<<<CB, 256>>>(Wg, Wd, bd, tg);
    gemm_out_tc<<<dim3(128, 16), 256>>>(out);
}

// round 7
// speedup vs baseline: 3.9315x; 1.0347x over previous
#include <cuda_runtime.h>
#include <cuda_bf16.h>
#include <stdint.h>
#include <math.h>

#define NBANKS 16
#define D 32
#define NIN 3072
#define NOUT 1000
#define BATCH 8192
#define BN_EPS 1e-5f
#define CB 128
#define PB 128

// ---------------- device scratch ----------------
__device__ float g_px1[PB * NIN];
__device__ float g_px2[PB * NIN];
__device__ float g_scale[NIN];
__device__ float g_shift[NIN];
__device__ float g_bpart[PB * 64];
__device__ __nv_bfloat16 g_WpH[NIN * 64];   // folded input weights hi
__device__ __nv_bfloat16 g_WpL[NIN * 64];   // folded input weights lo
__device__ float g_bp[64];
__device__ float g_in0[BATCH * D];
__device__ float g_in1[BATCH * D];
__device__ __nv_bfloat16 g_preTH[64 * BATCH];  // banks14,15 NORMALIZED acts, [k][row]
__device__ __nv_bfloat16 g_preTL[64 * BATCH];
__device__ __nv_bfloat16 g_WoutH[64 * 1024];   // Wout split, [k][n] pad 1024
__device__ __nv_bfloat16 g_WoutL[64 * 1024];
__device__ float g_p1s[NBANKS * CB * 32];
__device__ float g_p2s[NBANKS * CB * 32];
__device__ unsigned g_barc;
__device__ unsigned g_barg;
__device__ float g_tg_fallback[BATCH];

// ---------------- helpers ----------------
__device__ __forceinline__ unsigned smem_u32(const void* p) {
    return (unsigned)__cvta_generic_to_shared(p);
}
__device__ __forceinline__ void ldsm_x4(unsigned& r0, unsigned& r1, unsigned& r2,
                                        unsigned& r3, unsigned addr) {
    asm volatile("ldmatrix.sync.aligned.m8n8.x4.shared.b16 {%0,%1,%2,%3},[%4];"
                 : "=r"(r0), "=r"(r1), "=r"(r2), "=r"(r3) : "r"(addr));
}
__device__ __forceinline__ void ldsm_x4_t(unsigned& r0, unsigned& r1, unsigned& r2,
                                          unsigned& r3, unsigned addr) {
    asm volatile("ldmatrix.sync.aligned.m8n8.x4.trans.shared.b16 {%0,%1,%2,%3},[%4];"
                 : "=r"(r0), "=r"(r1), "=r"(r2), "=r"(r3) : "r"(addr));
}
__device__ __forceinline__ void mma_bf16(float* c, const unsigned* a,
                                         unsigned b0, unsigned b1) {
    asm volatile(
        "mma.sync.aligned.m16n8k16.row.col.f32.bf16.bf16.f32 "
        "{%0,%1,%2,%3},{%4,%5,%6,%7},{%8,%9},{%0,%1,%2,%3};"
        : "+f"(c[0]), "+f"(c[1]), "+f"(c[2]), "+f"(c[3])
        : "r"(a[0]), "r"(a[1]), "r"(a[2]), "r"(a[3]), "r"(b0), "r"(b1));
}
__device__ __forceinline__ unsigned pack_hi2(float x, float y) {
    __nv_bfloat16 hx = __float2bfloat16(x), hy = __float2bfloat16(y);
    return ((unsigned)__bfloat16_as_ushort(hy) << 16) | __bfloat16_as_ushort(hx);
}
__device__ __forceinline__ unsigned pack_lo2(float x, float y) {
    __nv_bfloat16 hx = __float2bfloat16(x), hy = __float2bfloat16(y);
    float lx = x - __bfloat162float(hx), ly = y - __bfloat162float(hy);
    __nv_bfloat16 bx = __float2bfloat16(lx), by = __float2bfloat16(ly);
    return ((unsigned)__bfloat16_as_ushort(by) << 16) | __bfloat16_as_ushort(bx);
}

// ---------------- grid barrier ----------------
__device__ __forceinline__ void grid_bar_n(int nblk) {
    __syncthreads();
    if (threadIdx.x == 0) {
        unsigned gen = *(volatile unsigned*)&g_barg;
        __threadfence();
        if (atomicAdd(&g_barc, 1u) == (unsigned)nblk - 1) {
            atomicExch(&g_barc, 0u);
            __threadfence();
            *(volatile unsigned*)&g_barg = gen + 1;
        } else {
            while (*(volatile unsigned*)&g_barg == gen) { }
        }
        __threadfence();
    }
    __syncthreads();
}

// ---------------- fused prep: x stats + BN fold + weight/bias fold ----------
// grid PB=128 blocks x 256 threads, 3 grid barriers.
__global__ void __launch_bounds__(256, 1) prep_kernel(
    const float* __restrict__ x, const float* __restrict__ gamma,
    const float* __restrict__ beta, const float* __restrict__ W_in,
    const float* __restrict__ b_in) {
    int tid = threadIdx.x;
    int blk = blockIdx.x;
    int warp = tid >> 5, lane = tid & 31;

    // phase 1: per-block column stats over rows [blk*64, +64)
    {
        float s1[3][4], s2[3][4];
        #pragma unroll
        for (int g = 0; g < 3; g++)
            #pragma unroll
            for (int i = 0; i < 4; i++) { s1[g][i] = 0.f; s2[g][i] = 0.f; }
        int row0 = blk * 64;
        for (int r = 0; r < 64; r++) {
            const float* xr = x + (size_t)(row0 + r) * NIN;
            #pragma unroll
            for (int g = 0; g < 3; g++) {
                float4 v = *(const float4*)&xr[g * 1024 + tid * 4];
                s1[g][0] += v.x; s2[g][0] += v.x * v.x;
                s1[g][1] += v.y; s2[g][1] += v.y * v.y;
                s1[g][2] += v.z; s2[g][2] += v.z * v.z;
                s1[g][3] += v.w; s2[g][3] += v.w * v.w;
            }
        }
        #pragma unroll
        for (int g = 0; g < 3; g++) {
            *(float4*)&g_px1[blk * NIN + g * 1024 + tid * 4] =
                make_float4(s1[g][0], s1[g][1], s1[g][2], s1[g][3]);
            *(float4*)&g_px2[blk * NIN + g * 1024 + tid * 4] =
                make_float4(s2[g][0], s2[g][1], s2[g][2], s2[g][3]);
        }
    }
    grid_bar_n(PB);
    // phase 2: finalize scale/shift for cols [blk*24, +24); 3 cols per warp
    {
        #pragma unroll
        for (int cc = 0; cc < 3; cc++) {
            int col = blk * 24 + warp * 3 + cc;
            float a = 0.f, b = 0.f;
            #pragma unroll
            for (int q = 0; q < 4; q++) {
                a += g_px1[(lane + q * 32) * NIN + col];
                b += g_px2[(lane + q * 32) * NIN + col];
            }
            #pragma unroll
            for (int o = 16; o; o >>= 1) {
                a += __shfl_xor_sync(~0u, a, o);
                b += __shfl_xor_sync(~0u, b, o);
            }
            if (lane == 0) {
                float mean = a * (1.f / BATCH);
                float var = b * (1.f / BATCH) - mean * mean;
                float rstd = rsqrtf(var + BN_EPS);
                float sc = rstd * gamma[col];
                g_scale[col] = sc;
                g_shift[col] = beta[col] - mean * sc;
            }
        }
    }
    grid_bar_n(PB);
    // phase 3: fold weights (bf16 split) + deterministic bias partials.
    // thread: fixed j = tid&63, group = tid>>6; c = blk*24 + group*6 + p.
    {
        __shared__ float sred[4][64];
        int j = tid & 63, grp = tid >> 6;
        int k = j >> 5, d = j & 31;
        float bias = 0.f;
        #pragma unroll
        for (int p = 0; p < 6; p++) {
            int c = blk * 24 + grp * 6 + p;
            float wraw = W_in[(size_t)k * NIN * D + c * D + d];
            float w = g_scale[c] * wraw;
            __nv_bfloat16 h = __float2bfloat16(w);
            g_WpH[c * 64 + j] = h;
            g_WpL[c * 64 + j] = __float2bfloat16(w - __bfloat162float(h));
            bias += g_shift[c] * wraw;
        }
        sred[grp][j] = bias;
        __syncthreads();
        if (tid < 64)
            g_bpart[blk * 64 + tid] =
                sred[0][tid] + sred[1][tid] + sred[2][tid] + sred[3][tid];
    }
    grid_bar_n(PB);
    // phase 4: block 0 combines bias partials
    if (blk == 0) {
        __shared__ float sred2[4][64];
        int j = tid & 63, grp = tid >> 6;
        float s = 0.f;
        #pragma unroll 8
        for (int b = grp; b < PB; b += 4) s += g_bpart[b * 64 + j];
        sred2[grp][j] = s;
        __syncthreads();
        if (tid < 64)
            g_bp[tid] = b_in[tid] +
                sred2[0][tid] + sred2[1][tid] + sred2[2][tid] + sred2[3][tid];
    }
}

// Wout split (no BN fold — acts are pre-normalized). grid 4 x 256.
__global__ void woutfold_kernel(const float* __restrict__ Wout) {
    int n = blockIdx.x * 256 + threadIdx.x;   // 0..1023
    #pragma unroll 8
    for (int k = 0; k < 64; k++) {
        int bank = k >> 5, d = k & 31;
        float w = (n < NOUT) ? Wout[(size_t)bank * D * NOUT + d * NOUT + n] : 0.f;
        __nv_bfloat16 h = __float2bfloat16(w);
        g_WoutH[k * 1024 + n] = h;
        g_WoutL[k * 1024 + n] = __float2bfloat16(w - __bfloat162float(h));
    }
}

// ---------------- input GEMM (tensor core, bf16 3-pass, double-buffered) ----
#define APAD 40
#define BPAD 72
__global__ void __launch_bounds__(256) gemm_in_tc(const float* __restrict__ x) {
    __shared__ __nv_bfloat16 Ah[2][64 * APAD];
    __shared__ __nv_bfloat16 Al[2][64 * APAD];
    __shared__ __nv_bfloat16 Bh[2][32 * BPAD];
    __shared__ __nv_bfloat16 Bl[2][32 * BPAD];
    int tid = threadIdx.x;
    int w = tid >> 5, l = tid & 31;
    int wm = w & 3, wn = w >> 2;
    int rowBase = blockIdx.x * 64;

    int a_r0 = tid >> 3;
    int a_k4 = (tid & 7) * 4;
    int b_kk = tid >> 3;
    int b_n8 = (tid & 7) * 8;

    float4 pa0, pa1;
    uint4 pbh, pbl;
    pa0 = *(const float4*)&x[(size_t)(rowBase + a_r0) * NIN + a_k4];
    pa1 = *(const float4*)&x[(size_t)(rowBase + a_r0 + 32) * NIN + a_k4];
    pbh = *(const uint4*)&g_WpH[b_kk * 64 + b_n8];
    pbl = *(const uint4*)&g_WpL[b_kk * 64 + b_n8];
    {
        uint2 h0, l0;
        h0.x = pack_hi2(pa0.x, pa0.y); h0.y = pack_hi2(pa0.z, pa0.w);
        l0.x = pack_lo2(pa0.x, pa0.y); l0.y = pack_lo2(pa0.z, pa0.w);
        *(uint2*)&Ah[0][a_r0 * APAD + a_k4] = h0;
        *(uint2*)&Al[0][a_r0 * APAD + a_k4] = l0;
        h0.x = pack_hi2(pa1.x, pa1.y); h0.y = pack_hi2(pa1.z, pa1.w);
        l0.x = pack_lo2(pa1.x, pa1.y); l0.y = pack_lo2(pa1.z, pa1.w);
        *(uint2*)&Ah[0][(a_r0 + 32) * APAD + a_k4] = h0;
        *(uint2*)&Al[0][(a_r0 + 32) * APAD + a_k4] = l0;
        *(uint4*)&Bh[0][b_kk * BPAD + b_n8] = pbh;
        *(uint4*)&Bl[0][b_kk * BPAD + b_n8] = pbl;
    }
    __syncthreads();

    float c[4][4];
    #pragma unroll
    for (int i = 0; i < 4; i++)
        #pragma unroll
        for (int j = 0; j < 4; j++) c[i][j] = 0.f;

    int a_row = wm * 16 + (l & 7) + ((l >> 3) & 1) * 8;
    int a_kof = (l >> 4) * 8;
    int b_k = (l & 7) + ((l >> 3) & 1) * 8;
    int b_n = (l >> 4) * 8;

    for (int kt = 0; kt < 96; kt++) {
        int cur = kt & 1, nxt = cur ^ 1;
        if (kt < 95) {
            int kb = (kt + 1) * 32;
            pa0 = *(const float4*)&x[(size_t)(rowBase + a_r0) * NIN + kb + a_k4];
            pa1 = *(const float4*)&x[(size_t)(rowBase + a_r0 + 32) * NIN + kb + a_k4];
            pbh = *(const uint4*)&g_WpH[(kb + b_kk) * 64 + b_n8];
            pbl = *(const uint4*)&g_WpL[(kb + b_kk) * 64 + b_n8];
        }
        unsigned ahb = smem_u32(Ah[cur]), alb = smem_u32(Al[cur]);
        unsigned bhb = smem_u32(Bh[cur]), blb = smem_u32(Bl[cur]);
        #pragma unroll
        for (int ks = 0; ks < 2; ks++) {
            int k0 = ks * 16;
            unsigned a_off = (unsigned)(a_row * (APAD * 2) + (k0 + a_kof) * 2);
            unsigned ah[4], al[4];
            ldsm_x4(ah[0], ah[1], ah[2], ah[3], ahb + a_off);
            ldsm_x4(al[0], al[1], al[2], al[3], alb + a_off);
            #pragma unroll
            for (int g = 0; g < 2; g++) {
                int n0 = wn * 32 + g * 16;
                unsigned b_off = (unsigned)((k0 + b_k) * (BPAD * 2) + (n0 + b_n) * 2);
                unsigned h0, h1, h2, h3, q0, q1, q2, q3;
                ldsm_x4_t(h0, h1, h2, h3, bhb + b_off);
                ldsm_x4_t(q0, q1, q2, q3, blb + b_off);
                mma_bf16(c[2 * g],     ah, h0, h1);
                mma_bf16(c[2 * g + 1], ah, h2, h3);
                mma_bf16(c[2 * g],     ah, q0, q1);
                mma_bf16(c[2 * g + 1], ah, q2, q3);
                mma_bf16(c[2 * g],     al, h0, h1);
                mma_bf16(c[2 * g + 1], al, h2, h3);
            }
        }
        if (kt < 95) {
            uint2 h0, l0;
            h0.x = pack_hi2(pa0.x, pa0.y); h0.y = pack_hi2(pa0.z, pa0.w);
            l0.x = pack_lo2(pa0.x, pa0.y); l0.y = pack_lo2(pa0.z, pa0.w);
            *(uint2*)&Ah[nxt][a_r0 * APAD + a_k4] = h0;
            *(uint2*)&Al[nxt][a_r0 * APAD + a_k4] = l0;
            h0.x = pack_hi2(pa1.x, pa1.y); h0.y = pack_hi2(pa1.z, pa1.w);
            l0.x = pack_lo2(pa1.x, pa1.y); l0.y = pack_lo2(pa1.z, pa1.w);
            *(uint2*)&Ah[nxt][(a_r0 + 32) * APAD + a_k4] = h0;
            *(uint2*)&Al[nxt][(a_r0 + 32) * APAD + a_k4] = l0;
            *(uint4*)&Bh[nxt][b_kk * BPAD + b_n8] = pbh;
            *(uint4*)&Bl[nxt][b_kk * BPAD + b_n8] = pbl;
        }
        __syncthreads();
    }
    int r0 = rowBase + wm * 16 + (l >> 2);
    #pragma unroll
    for (int nb = 0; nb < 4; nb++) {
        int col = wn * 32 + nb * 8 + (l & 3) * 2;
        float2 bp = *(const float2*)&g_bp[col];
        float2 v0, v1;
        v0.x = fmaxf(c[nb][0] + bp.x, 0.f);
        v0.y = fmaxf(c[nb][1] + bp.y, 0.f);
        v1.x = fmaxf(c[nb][2] + bp.x, 0.f);
        v1.y = fmaxf(c[nb][3] + bp.y, 0.f);
        if (col < 32) {
            *(float2*)&g_in0[r0 * D + col] = v0;
            *(float2*)&g_in0[(r0 + 8) * D + col] = v1;
        } else {
            *(float2*)&g_in1[r0 * D + col - 32] = v0;
            *(float2*)&g_in1[(r0 + 8) * D + col - 32] = v1;
        }
    }
}

// ---------------- persistent bank-chain kernel (normalize-in-place) --------
__global__ void __launch_bounds__(256, 1) chain_kernel(
    const float* __restrict__ Wg, const float* __restrict__ Wd,
    const float* __restrict__ bd, float* __restrict__ tg) {
    __shared__ __align__(16) float actT[4][32][68];   // NORMALIZED acts window
    __shared__ float sgraw[4][64];
    __shared__ float stg[64];
    __shared__ float smean[4][32], srstd[4][32];
    __shared__ float red1[8][32], red2[8][32];

    int tid = threadIdx.x;
    int blk = blockIdx.x;
    int rowBase = blk * 64;
    int j0 = (tid & 15) * 2, r0 = (tid >> 4) * 4;
    int warp = tid >> 5, lane = tid & 31;
    int grow = tid & 63, gei = tid >> 6;
    int nd = tid >> 3, nrg = (tid & 7) * 8;
    if (tid < 64) stg[tid] = 0.f;

    for (int t = 0; t < 16; t++) {
        int s0 = (t - 4 < 0) ? 0 : t - 4;
        int ecnt = (t < 4) ? t : 4;
        int ebase = (t <= 1) ? 0 : (t == 2) ? 1 : (t == 3) ? 3 : (t == 4) ? 6 : 10 + (t - 5) * 4;

        if (ecnt > 0) {
            if (gei < ecnt) {
                int e = ebase + gei, slot = (s0 + gei) & 3;
                const float* wgp = Wg + e * 32;
                float g = 0.f;
                #pragma unroll
                for (int k = 0; k < 32; k++)
                    g += actT[slot][k][grow] * __ldg(&wgp[k]);
                sgraw[gei][grow] = g;
            }
            __syncthreads();
        }

        float acc[4][2];
        if (t <= 1) {
            const float* src = (t == 0) ? g_in0 : g_in1;
            #pragma unroll
            for (int i = 0; i < 4; i++) {
                float2 v = *(const float2*)&src[(rowBase + r0 + i) * D + j0];
                acc[i][0] = v.x; acc[i][1] = v.y;
            }
        } else {
            #pragma unroll
            for (int i = 0; i < 4; i++) { acc[i][0] = 0.f; acc[i][1] = 0.f; }
        }
        for (int ei = 0; ei < ecnt; ei++) {
            int e = ebase + ei, slot = (s0 + ei) & 3;
            float gi[4];
            #pragma unroll
            for (int i = 0; i < 4; i++)
                gi[i] = fminf(fmaxf(sgraw[ei][r0 + i], 0.f), 1.f);
            if ((tid & 15) == 0) {
                #pragma unroll
                for (int i = 0; i < 4; i++) stg[r0 + i] += gi[i];
            }
            float2 b2 = __ldg((const float2*)&bd[e * 32 + j0]);
            float dat[4][2];
            #pragma unroll
            for (int i = 0; i < 4; i++) { dat[i][0] = b2.x; dat[i][1] = b2.y; }
            const float* wp = Wd + e * 1024 + j0;
            #pragma unroll
            for (int k = 0; k < 32; k++) {
                float4 a4 = *(const float4*)&actT[slot][k][r0];
                float2 w2 = __ldg((const float2*)&wp[k * 32]);
                dat[0][0] += a4.x * w2.x; dat[0][1] += a4.x * w2.y;
                dat[1][0] += a4.y * w2.x; dat[1][1] += a4.y * w2.y;
                dat[2][0] += a4.z * w2.x; dat[2][1] += a4.z * w2.y;
                dat[3][0] += a4.w * w2.x; dat[3][1] += a4.w * w2.y;
            }
            #pragma unroll
            for (int i = 0; i < 4; i++) {
                acc[i][0] += gi[i] * dat[i][0];
                acc[i][1] += gi[i] * dat[i][1];
            }
        }

        int slot_t = t & 3;
        #pragma unroll
        for (int cc = 0; cc < 2; cc++) {
            float4 st = make_float4(fmaxf(acc[0][cc], 0.f), fmaxf(acc[1][cc], 0.f),
                                    fmaxf(acc[2][cc], 0.f), fmaxf(acc[3][cc], 0.f));
            *(float4*)&actT[slot_t][j0 + cc][r0] = st;
        }
        __syncthreads();

        {
            float s1 = 0.f, s2 = 0.f;
            #pragma unroll
            for (int q = 0; q < 8; q++) {
                float xv = actT[slot_t][lane][warp * 8 + q];
                s1 += xv; s2 += xv * xv;
            }
            red1[warp][lane] = s1;
            red2[warp][lane] = s2;
        }
        __syncthreads();
        if (warp == 0) {
            float s1 = 0.f, s2 = 0.f;
            #pragma unroll
            for (int g2 = 0; g2 < 8; g2++) { s1 += red1[g2][lane]; s2 += red2[g2][lane]; }
            g_p1s[(t * CB + blk) * 32 + lane] = s1;
            g_p2s[(t * CB + blk) * 32 + lane] = s2;
        }
        grid_bar_n(CB);
        {
            float s1 = 0.f, s2 = 0.f;
            #pragma unroll 4
            for (int b = warp; b < CB; b += 8) {
                s1 += __ldcg(&g_p1s[(t * CB + b) * 32 + lane]);
                s2 += __ldcg(&g_p2s[(t * CB + b) * 32 + lane]);
            }
            red1[warp][lane] = s1;
            red2[warp][lane] = s2;
        }
        __syncthreads();
        if (warp == 0) {
            float s1 = 0.f, s2 = 0.f;
            #pragma unroll
            for (int g2 = 0; g2 < 8; g2++) { s1 += red1[g2][lane]; s2 += red2[g2][lane]; }
            float mean = s1 * (1.f / BATCH);
            float var = s2 * (1.f / BATCH) - mean * mean;
            smean[slot_t][lane] = mean;
            srstd[slot_t][lane] = rsqrtf(var + BN_EPS);
        }
        __syncthreads();
        {
            float m = smean[slot_t][nd], r = srstd[slot_t][nd];
            #pragma unroll
            for (int q2 = 0; q2 < 2; q2++) {
                float4 vv = *(float4*)&actT[slot_t][nd][nrg + q2 * 4];
                vv.x = (vv.x - m) * r; vv.y = (vv.y - m) * r;
                vv.z = (vv.z - m) * r; vv.w = (vv.w - m) * r;
                *(float4*)&actT[slot_t][nd][nrg + q2 * 4] = vv;
                if (t >= 14) {
                    int krow = (t - 14) * 32 + nd;
                    uint2 hv, lv;
                    hv.x = pack_hi2(vv.x, vv.y); hv.y = pack_hi2(vv.z, vv.w);
                    lv.x = pack_lo2(vv.x, vv.y); lv.y = pack_lo2(vv.z, vv.w);
                    *(uint2*)&g_preTH[krow * BATCH + rowBase + nrg + q2 * 4] = hv;
                    *(uint2*)&g_preTL[krow * BATCH + rowBase + nrg + q2 * 4] = lv;
                }
            }
        }
        __syncthreads();
    }
    if (tid < 64) tg[rowBase + tid] = stg[tid];
}

// ---------------- output GEMM (tensor core, no bias) ----------------
#define ATM 72
#define AST 72
__global__ void __launch_bounds__(256) gemm_out_tc(float* __restrict__ out) {
    __shared__ __nv_bfloat16 ATh[64 * ATM];
    __shared__ __nv_bfloat16 ATl[64 * ATM];
    __shared__ __nv_bfloat16 Bh[64 * AST];
    __shared__ __nv_bfloat16 Bl[64 * AST];
    int tid = threadIdx.x;
    int w = tid >> 5, l = tid & 31;
    int wm = w & 3, wn = w >> 2;
    int rowBase = blockIdx.x * 64;
    int colBase = blockIdx.y * 64;
    unsigned ah_b = smem_u32(ATh), al_b = smem_u32(ATl);
    unsigned bh_b = smem_u32(Bh), bl_b = smem_u32(Bl);

    #pragma unroll
    for (int p = 0; p < 2; p++) {
        int idx = p * 256 + tid;
        int k = idx >> 3;
        int m8 = (idx & 7) * 8;
        *(uint4*)&ATh[k * ATM + m8] = *(const uint4*)&g_preTH[k * BATCH + rowBase + m8];
        *(uint4*)&ATl[k * ATM + m8] = *(const uint4*)&g_preTL[k * BATCH + rowBase + m8];
    }
    #pragma unroll
    for (int p = 0; p < 2; p++) {
        int idx = p * 256 + tid;
        int k = idx >> 3;
        int n8 = (idx & 7) * 8;
        *(uint4*)&Bh[k * AST + n8] = *(const uint4*)&g_WoutH[k * 1024 + colBase + n8];
        *(uint4*)&Bl[k * AST + n8] = *(const uint4*)&g_WoutL[k * 1024 + colBase + n8];
    }
    __syncthreads();

    float c[4][4];
    #pragma unroll
    for (int i = 0; i < 4; i++)
        #pragma unroll
        for (int j = 0; j < 4; j++) c[i][j] = 0.f;

    int a_k = (l & 7) + (l >> 4) * 8;
    int a_m = wm * 16 + ((l >> 3) & 1) * 8;
    int b_k = (l & 7) + ((l >> 3) & 1) * 8;
    int b_n = (l >> 4) * 8;

    #pragma unroll
    for (int ks = 0; ks < 4; ks++) {
        int k0 = ks * 16;
        unsigned a_off = (unsigned)((k0 + a_k) * (ATM * 2) + a_m * 2);
        unsigned ah[4], al[4];
        ldsm_x4_t(ah[0], ah[1], ah[2], ah[3], ah_b + a_off);
        ldsm_x4_t(al[0], al[1], al[2], al[3], al_b + a_off);
        #pragma unroll
        for (int g = 0; g < 2; g++) {
            int n0 = wn * 32 + g * 16;
            unsigned b_off = (unsigned)((k0 + b_k) * (AST * 2) + (n0 + b_n) * 2);
            unsigned h0, h1, h2, h3, q0, q1, q2, q3;
            ldsm_x4_t(h0, h1, h2, h3, bh_b + b_off);
            ldsm_x4_t(q0, q1, q2, q3, bl_b + b_off);
            mma_bf16(c[2 * g],     ah, h0, h1);
            mma_bf16(c[2 * g + 1], ah, h2, h3);
            mma_bf16(c[2 * g],     ah, q0, q1);
            mma_bf16(c[2 * g + 1], ah, q2, q3);
            mma_bf16(c[2 * g],     al, h0, h1);
            mma_bf16(c[2 * g + 1], al, h2, h3);
        }
    }
    int r0 = rowBase + wm * 16 + (l >> 2);
    #pragma unroll
    for (int nb = 0; nb < 4; nb++) {
        int col = colBase + wn * 32 + nb * 8 + (l & 3) * 2;
        if (col < NOUT) {
            float2 v0 = make_float2(c[nb][0], c[nb][1]);
            float2 v1 = make_float2(c[nb][2], c[nb][3]);
            *(float2*)&out[(size_t)r0 * NOUT + col] = v0;
            *(float2*)&out[(size_t)(r0 + 8) * NOUT + col] = v1;
        }
    }
}

// ---------------- launch ----------------
extern "C" void kernel_launch(void* const* d_in, const int* in_sizes, int n_in,
                              void* d_out, int out_size) {
    const float* x     = (const float*)d_in[0];
    const float* gamma = (const float*)d_in[1];
    const float* beta  = (const float*)d_in[2];
    const float* W_in  = (const float*)d_in[3];
    const float* b_in  = (const float*)d_in[4];
    const float* Wg    = (const float*)d_in[5];
    const float* Wd    = (const float*)d_in[6];
    const float* bd    = (const float*)d_in[7];
    const float* Wout  = (const float*)d_in[8];
    float* out = (float*)d_out;

    float* tg;
    if (out_size >= BATCH * NOUT + BATCH) {
        tg = out + (size_t)BATCH * NOUT;
    } else {
        void* p = nullptr;
        cudaGetSymbolAddress(&p, g_tg_fallback);
        tg = (float*)p;
    }

    prep_kernel<<<PB, 256>>>(x, gamma, beta, W_in, b_in);
    woutfold_kernel<<<4, 256>>>(Wout);
    gemm_in_tc<<<128, 256>>>(x);
    chain_kernel<<<CB, 256>>>(Wg, Wd, bd, tg);   // 4th launch -> ncu target
    gemm_out_tc<<<dim3(128, 16), 256>>>(out);
}

// round 8
// speedup vs baseline: 3.9579x; 1.0067x over previous
#include <cuda_runtime.h>
#include <cuda_bf16.h>
#include <stdint.h>
#include <math.h>

#define NBANKS 16
#define D 32
#define NIN 3072
#define NOUT 1000
#define BATCH 8192
#define BN_EPS 1e-5f
#define CB 128
#define PB 128

// ---------------- device scratch ----------------
__device__ float g_px1[PB * NIN];
__device__ float g_px2[PB * NIN];
__device__ float g_scale[NIN];
__device__ float g_shift[NIN];
__device__ float g_bpart[PB * 64];
__device__ __nv_bfloat16 g_WpH[NIN * 64];
__device__ __nv_bfloat16 g_WpL[NIN * 64];
__device__ float g_bp[64];
__device__ float g_in0[BATCH * D];
__device__ float g_in1[BATCH * D];
__device__ __nv_bfloat16 g_preTH[64 * BATCH];
__device__ __nv_bfloat16 g_preTL[64 * BATCH];
__device__ __nv_bfloat16 g_WoutH[64 * 1024];
__device__ __nv_bfloat16 g_WoutL[64 * 1024];
__device__ float g_p1s[NBANKS * CB * 32];
__device__ float g_p2s[NBANKS * CB * 32];
__device__ unsigned g_barc;
__device__ unsigned g_barg;
__device__ float g_tg_fallback[BATCH];

// ---------------- helpers ----------------
__device__ __forceinline__ unsigned smem_u32(const void* p) {
    return (unsigned)__cvta_generic_to_shared(p);
}
__device__ __forceinline__ void ldsm_x4(unsigned& r0, unsigned& r1, unsigned& r2,
                                        unsigned& r3, unsigned addr) {
    asm volatile("ldmatrix.sync.aligned.m8n8.x4.shared.b16 {%0,%1,%2,%3},[%4];"
                 : "=r"(r0), "=r"(r1), "=r"(r2), "=r"(r3) : "r"(addr));
}
__device__ __forceinline__ void ldsm_x4_t(unsigned& r0, unsigned& r1, unsigned& r2,
                                          unsigned& r3, unsigned addr) {
    asm volatile("ldmatrix.sync.aligned.m8n8.x4.trans.shared.b16 {%0,%1,%2,%3},[%4];"
                 : "=r"(r0), "=r"(r1), "=r"(r2), "=r"(r3) : "r"(addr));
}
__device__ __forceinline__ void mma_bf16(float* c, const unsigned* a,
                                         unsigned b0, unsigned b1) {
    asm volatile(
        "mma.sync.aligned.m16n8k16.row.col.f32.bf16.bf16.f32 "
        "{%0,%1,%2,%3},{%4,%5,%6,%7},{%8,%9},{%0,%1,%2,%3};"
        : "+f"(c[0]), "+f"(c[1]), "+f"(c[2]), "+f"(c[3])
        : "r"(a[0]), "r"(a[1]), "r"(a[2]), "r"(a[3]), "r"(b0), "r"(b1));
}
__device__ __forceinline__ unsigned pack_hi2(float x, float y) {
    __nv_bfloat16 hx = __float2bfloat16(x), hy = __float2bfloat16(y);
    return ((unsigned)__bfloat16_as_ushort(hy) << 16) | __bfloat16_as_ushort(hx);
}
__device__ __forceinline__ unsigned pack_lo2(float x, float y) {
    __nv_bfloat16 hx = __float2bfloat16(x), hy = __float2bfloat16(y);
    float lx = x - __bfloat162float(hx), ly = y - __bfloat162float(hy);
    __nv_bfloat16 bx = __float2bfloat16(lx), by = __float2bfloat16(ly);
    return ((unsigned)__bfloat16_as_ushort(by) << 16) | __bfloat16_as_ushort(bx);
}

// ---------------- grid barrier ----------------
__device__ __forceinline__ void grid_bar_n(int nblk) {
    __syncthreads();
    if (threadIdx.x == 0) {
        unsigned gen = *(volatile unsigned*)&g_barg;
        __threadfence();
        if (atomicAdd(&g_barc, 1u) == (unsigned)nblk - 1) {
            atomicExch(&g_barc, 0u);
            __threadfence();
            *(volatile unsigned*)&g_barg = gen + 1;
        } else {
            while (*(volatile unsigned*)&g_barg == gen) { }
        }
        __threadfence();
    }
    __syncthreads();
}

// ---------------- fused prep ----------------
__global__ void __launch_bounds__(256, 1) prep_kernel(
    const float* __restrict__ x, const float* __restrict__ gamma,
    const float* __restrict__ beta, const float* __restrict__ W_in,
    const float* __restrict__ b_in) {
    int tid = threadIdx.x;
    int blk = blockIdx.x;
    int warp = tid >> 5, lane = tid & 31;

    {
        float s1[3][4], s2[3][4];
        #pragma unroll
        for (int g = 0; g < 3; g++)
            #pragma unroll
            for (int i = 0; i < 4; i++) { s1[g][i] = 0.f; s2[g][i] = 0.f; }
        int row0 = blk * 64;
        for (int r = 0; r < 64; r++) {
            const float* xr = x + (size_t)(row0 + r) * NIN;
            #pragma unroll
            for (int g = 0; g < 3; g++) {
                float4 v = *(const float4*)&xr[g * 1024 + tid * 4];
                s1[g][0] += v.x; s2[g][0] += v.x * v.x;
                s1[g][1] += v.y; s2[g][1] += v.y * v.y;
                s1[g][2] += v.z; s2[g][2] += v.z * v.z;
                s1[g][3] += v.w; s2[g][3] += v.w * v.w;
            }
        }
        #pragma unroll
        for (int g = 0; g < 3; g++) {
            *(float4*)&g_px1[blk * NIN + g * 1024 + tid * 4] =
                make_float4(s1[g][0], s1[g][1], s1[g][2], s1[g][3]);
            *(float4*)&g_px2[blk * NIN + g * 1024 + tid * 4] =
                make_float4(s2[g][0], s2[g][1], s2[g][2], s2[g][3]);
        }
    }
    grid_bar_n(PB);
    {
        #pragma unroll
        for (int cc = 0; cc < 3; cc++) {
            int col = blk * 24 + warp * 3 + cc;
            float a = 0.f, b = 0.f;
            #pragma unroll
            for (int q = 0; q < 4; q++) {
                a += g_px1[(lane + q * 32) * NIN + col];
                b += g_px2[(lane + q * 32) * NIN + col];
            }
            #pragma unroll
            for (int o = 16; o; o >>= 1) {
                a += __shfl_xor_sync(~0u, a, o);
                b += __shfl_xor_sync(~0u, b, o);
            }
            if (lane == 0) {
                float mean = a * (1.f / BATCH);
                float var = b * (1.f / BATCH) - mean * mean;
                float rstd = rsqrtf(var + BN_EPS);
                float sc = rstd * gamma[col];
                g_scale[col] = sc;
                g_shift[col] = beta[col] - mean * sc;
            }
        }
    }
    grid_bar_n(PB);
    {
        __shared__ float sred[4][64];
        int j = tid & 63, grp = tid >> 6;
        int k = j >> 5, d = j & 31;
        float bias = 0.f;
        #pragma unroll
        for (int p = 0; p < 6; p++) {
            int c = blk * 24 + grp * 6 + p;
            float wraw = W_in[(size_t)k * NIN * D + c * D + d];
            float w = g_scale[c] * wraw;
            __nv_bfloat16 h = __float2bfloat16(w);
            g_WpH[c * 64 + j] = h;
            g_WpL[c * 64 + j] = __float2bfloat16(w - __bfloat162float(h));
            bias += g_shift[c] * wraw;
        }
        sred[grp][j] = bias;
        __syncthreads();
        if (tid < 64)
            g_bpart[blk * 64 + tid] =
                sred[0][tid] + sred[1][tid] + sred[2][tid] + sred[3][tid];
    }
    grid_bar_n(PB);
    if (blk == 0) {
        __shared__ float sred2[4][64];
        int j = tid & 63, grp = tid >> 6;
        float s = 0.f;
        #pragma unroll 8
        for (int b = grp; b < PB; b += 4) s += g_bpart[b * 64 + j];
        sred2[grp][j] = s;
        __syncthreads();
        if (tid < 64)
            g_bp[tid] = b_in[tid] +
                sred2[0][tid] + sred2[1][tid] + sred2[2][tid] + sred2[3][tid];
    }
}

__global__ void woutfold_kernel(const float* __restrict__ Wout) {
    int n = blockIdx.x * 256 + threadIdx.x;
    #pragma unroll 8
    for (int k = 0; k < 64; k++) {
        int bank = k >> 5, d = k & 31;
        float w = (n < NOUT) ? Wout[(size_t)bank * D * NOUT + d * NOUT + n] : 0.f;
        __nv_bfloat16 h = __float2bfloat16(w);
        g_WoutH[k * 1024 + n] = h;
        g_WoutL[k * 1024 + n] = __float2bfloat16(w - __bfloat162float(h));
    }
}

// ---------------- input GEMM (unchanged) ----------------
#define APAD 40
#define BPAD 72
__global__ void __launch_bounds__(256) gemm_in_tc(const float* __restrict__ x) {
    __shared__ __nv_bfloat16 Ah[2][64 * APAD];
    __shared__ __nv_bfloat16 Al[2][64 * APAD];
    __shared__ __nv_bfloat16 Bh[2][32 * BPAD];
    __shared__ __nv_bfloat16 Bl[2][32 * BPAD];
    int tid = threadIdx.x;
    int w = tid >> 5, l = tid & 31;
    int wm = w & 3, wn = w >> 2;
    int rowBase = blockIdx.x * 64;

    int a_r0 = tid >> 3;
    int a_k4 = (tid & 7) * 4;
    int b_kk = tid >> 3;
    int b_n8 = (tid & 7) * 8;

    float4 pa0, pa1;
    uint4 pbh, pbl;
    pa0 = *(const float4*)&x[(size_t)(rowBase + a_r0) * NIN + a_k4];
    pa1 = *(const float4*)&x[(size_t)(rowBase + a_r0 + 32) * NIN + a_k4];
    pbh = *(const uint4*)&g_WpH[b_kk * 64 + b_n8];
    pbl = *(const uint4*)&g_WpL[b_kk * 64 + b_n8];
    {
        uint2 h0, l0;
        h0.x = pack_hi2(pa0.x, pa0.y); h0.y = pack_hi2(pa0.z, pa0.w);
        l0.x = pack_lo2(pa0.x, pa0.y); l0.y = pack_lo2(pa0.z, pa0.w);
        *(uint2*)&Ah[0][a_r0 * APAD + a_k4] = h0;
        *(uint2*)&Al[0][a_r0 * APAD + a_k4] = l0;
        h0.x = pack_hi2(pa1.x, pa1.y); h0.y = pack_hi2(pa1.z, pa1.w);
        l0.x = pack_lo2(pa1.x, pa1.y); l0.y = pack_lo2(pa1.z, pa1.w);
        *(uint2*)&Ah[0][(a_r0 + 32) * APAD + a_k4] = h0;
        *(uint2*)&Al[0][(a_r0 + 32) * APAD + a_k4] = l0;
        *(uint4*)&Bh[0][b_kk * BPAD + b_n8] = pbh;
        *(uint4*)&Bl[0][b_kk * BPAD + b_n8] = pbl;
    }
    __syncthreads();

    float c[4][4];
    #pragma unroll
    for (int i = 0; i < 4; i++)
        #pragma unroll
        for (int j = 0; j < 4; j++) c[i][j] = 0.f;

    int a_row = wm * 16 + (l & 7) + ((l >> 3) & 1) * 8;
    int a_kof = (l >> 4) * 8;
    int b_k = (l & 7) + ((l >> 3) & 1) * 8;
    int b_n = (l >> 4) * 8;

    for (int kt = 0; kt < 96; kt++) {
        int cur = kt & 1, nxt = cur ^ 1;
        if (kt < 95) {
            int kb = (kt + 1) * 32;
            pa0 = *(const float4*)&x[(size_t)(rowBase + a_r0) * NIN + kb + a_k4];
            pa1 = *(const float4*)&x[(size_t)(rowBase + a_r0 + 32) * NIN + kb + a_k4];
            pbh = *(const uint4*)&g_WpH[(kb + b_kk) * 64 + b_n8];
            pbl = *(const uint4*)&g_WpL[(kb + b_kk) * 64 + b_n8];
        }
        unsigned ahb = smem_u32(Ah[cur]), alb = smem_u32(Al[cur]);
        unsigned bhb = smem_u32(Bh[cur]), blb = smem_u32(Bl[cur]);
        #pragma unroll
        for (int ks = 0; ks < 2; ks++) {
            int k0 = ks * 16;
            unsigned a_off = (unsigned)(a_row * (APAD * 2) + (k0 + a_kof) * 2);
            unsigned ah[4], al[4];
            ldsm_x4(ah[0], ah[1], ah[2], ah[3], ahb + a_off);
            ldsm_x4(al[0], al[1], al[2], al[3], alb + a_off);
            #pragma unroll
            for (int g = 0; g < 2; g++) {
                int n0 = wn * 32 + g * 16;
                unsigned b_off = (unsigned)((k0 + b_k) * (BPAD * 2) + (n0 + b_n) * 2);
                unsigned h0, h1, h2, h3, q0, q1, q2, q3;
                ldsm_x4_t(h0, h1, h2, h3, bhb + b_off);
                ldsm_x4_t(q0, q1, q2, q3, blb + b_off);
                mma_bf16(c[2 * g],     ah, h0, h1);
                mma_bf16(c[2 * g + 1], ah, h2, h3);
                mma_bf16(c[2 * g],     ah, q0, q1);
                mma_bf16(c[2 * g + 1], ah, q2, q3);
                mma_bf16(c[2 * g],     al, h0, h1);
                mma_bf16(c[2 * g + 1], al, h2, h3);
            }
        }
        if (kt < 95) {
            uint2 h0, l0;
            h0.x = pack_hi2(pa0.x, pa0.y); h0.y = pack_hi2(pa0.z, pa0.w);
            l0.x = pack_lo2(pa0.x, pa0.y); l0.y = pack_lo2(pa0.z, pa0.w);
            *(uint2*)&Ah[nxt][a_r0 * APAD + a_k4] = h0;
            *(uint2*)&Al[nxt][a_r0 * APAD + a_k4] = l0;
            h0.x = pack_hi2(pa1.x, pa1.y); h0.y = pack_hi2(pa1.z, pa1.w);
            l0.x = pack_lo2(pa1.x, pa1.y); l0.y = pack_lo2(pa1.z, pa1.w);
            *(uint2*)&Ah[nxt][(a_r0 + 32) * APAD + a_k4] = h0;
            *(uint2*)&Al[nxt][(a_r0 + 32) * APAD + a_k4] = l0;
            *(uint4*)&Bh[nxt][b_kk * BPAD + b_n8] = pbh;
            *(uint4*)&Bl[nxt][b_kk * BPAD + b_n8] = pbl;
        }
        __syncthreads();
    }
    int r0 = rowBase + wm * 16 + (l >> 2);
    #pragma unroll
    for (int nb = 0; nb < 4; nb++) {
        int col = wn * 32 + nb * 8 + (l & 3) * 2;
        float2 bp = *(const float2*)&g_bp[col];
        float2 v0, v1;
        v0.x = fmaxf(c[nb][0] + bp.x, 0.f);
        v0.y = fmaxf(c[nb][1] + bp.y, 0.f);
        v1.x = fmaxf(c[nb][2] + bp.x, 0.f);
        v1.y = fmaxf(c[nb][3] + bp.y, 0.f);
        if (col < 32) {
            *(float2*)&g_in0[r0 * D + col] = v0;
            *(float2*)&g_in0[(r0 + 8) * D + col] = v1;
        } else {
            *(float2*)&g_in1[r0 * D + col - 32] = v0;
            *(float2*)&g_in1[(r0 + 8) * D + col - 32] = v1;
        }
    }
}

// ---------------- persistent bank-chain kernel, 512 threads ----------------
__global__ void __launch_bounds__(512, 1) chain_kernel(
    const float* __restrict__ Wg, const float* __restrict__ Wd,
    const float* __restrict__ bd, float* __restrict__ tg) {
    __shared__ __align__(16) float actT[4][32][68];
    __shared__ float sgraw[4][64];
    __shared__ float stg[64];
    __shared__ float smean[4][32], srstd[4][32];
    __shared__ float red1[16][32], red2[16][32];

    int tid = threadIdx.x;
    int blk = blockIdx.x;
    int rowBase = blk * 64;
    int j0 = (tid & 15) * 2;          // col pair
    int r0 = (tid >> 4) * 2;          // row pair (0..62)
    int warp = tid >> 5, lane = tid & 31;
    int grow = tid & 63, gei = tid >> 6;      // gate mapping (8 groups, <=4 used)
    int nd = tid >> 4, nrg = (tid & 15) * 4;  // normalize: d 0..31, 4 rows
    if (tid < 64) stg[tid] = 0.f;

    for (int t = 0; t < 16; t++) {
        int s0 = (t - 4 < 0) ? 0 : t - 4;
        int ecnt = (t < 4) ? t : 4;
        int ebase = (t <= 1) ? 0 : (t == 2) ? 1 : (t == 3) ? 3 : (t == 4) ? 6 : 10 + (t - 5) * 4;

        // init accumulators early (independent global loads overlap gate stage)
        float acc[2][2];
        if (t <= 1) {
            const float* src = (t == 0) ? g_in0 : g_in1;
            #pragma unroll
            for (int i = 0; i < 2; i++) {
                float2 v = *(const float2*)&src[(rowBase + r0 + i) * D + j0];
                acc[i][0] = v.x; acc[i][1] = v.y;
            }
        } else {
            acc[0][0] = acc[0][1] = acc[1][0] = acc[1][1] = 0.f;
        }

        // --- gate stage ---
        if (ecnt > 0) {
            if (gei < ecnt) {
                int e = ebase + gei, slot = (s0 + gei) & 3;
                const float* wgp = Wg + e * 32;
                float g = 0.f;
                #pragma unroll
                for (int k = 0; k < 32; k++)
                    g += actT[slot][k][grow] * __ldg(&wgp[k]);
                sgraw[gei][grow] = g;
            }
            __syncthreads();
        }

        // --- gated accumulate: 2 rows x 2 cols per thread ---
        for (int ei = 0; ei < ecnt; ei++) {
            int e = ebase + ei, slot = (s0 + ei) & 3;
            float gi[2];
            gi[0] = fminf(fmaxf(sgraw[ei][r0], 0.f), 1.f);
            gi[1] = fminf(fmaxf(sgraw[ei][r0 + 1], 0.f), 1.f);
            if ((tid & 15) == 0) {
                stg[r0] += gi[0];
                stg[r0 + 1] += gi[1];
            }
            float2 b2 = __ldg((const float2*)&bd[e * 32 + j0]);
            float dat[2][2];
            dat[0][0] = b2.x; dat[0][1] = b2.y;
            dat[1][0] = b2.x; dat[1][1] = b2.y;
            const float* wp = Wd + e * 1024 + j0;
            #pragma unroll
            for (int k = 0; k < 32; k++) {
                float2 a2 = *(const float2*)&actT[slot][k][r0];
                float2 w2 = __ldg((const float2*)&wp[k * 32]);
                dat[0][0] += a2.x * w2.x; dat[0][1] += a2.x * w2.y;
                dat[1][0] += a2.y * w2.x; dat[1][1] += a2.y * w2.y;
            }
            acc[0][0] += gi[0] * dat[0][0];
            acc[0][1] += gi[0] * dat[0][1];
            acc[1][0] += gi[1] * dat[1][0];
            acc[1][1] += gi[1] * dat[1][1];
        }

        // --- relu + store transposed ---
        int slot_t = t & 3;
        #pragma unroll
        for (int cc = 0; cc < 2; cc++) {
            float2 st = make_float2(fmaxf(acc[0][cc], 0.f), fmaxf(acc[1][cc], 0.f));
            *(float2*)&actT[slot_t][j0 + cc][r0] = st;
        }
        __syncthreads();

        // --- per-block column-stat partials (16 warps x 4 rows) ---
        {
            float s1 = 0.f, s2 = 0.f;
            #pragma unroll
            for (int q = 0; q < 4; q++) {
                float xv = actT[slot_t][lane][warp * 4 + q];
                s1 += xv; s2 += xv * xv;
            }
            red1[warp][lane] = s1;
            red2[warp][lane] = s2;
        }
        __syncthreads();
        if (warp == 0) {
            float s1 = 0.f, s2 = 0.f;
            #pragma unroll
            for (int g2 = 0; g2 < 16; g2++) { s1 += red1[g2][lane]; s2 += red2[g2][lane]; }
            g_p1s[(t * CB + blk) * 32 + lane] = s1;
            g_p2s[(t * CB + blk) * 32 + lane] = s2;
        }
        grid_bar_n(CB);
        // --- finalize stats (16 warps x 8 blocks each) ---
        {
            float s1 = 0.f, s2 = 0.f;
            #pragma unroll 4
            for (int b = warp; b < CB; b += 16) {
                s1 += __ldcg(&g_p1s[(t * CB + b) * 32 + lane]);
                s2 += __ldcg(&g_p2s[(t * CB + b) * 32 + lane]);
            }
            red1[warp][lane] = s1;
            red2[warp][lane] = s2;
        }
        __syncthreads();
        if (warp == 0) {
            float s1 = 0.f, s2 = 0.f;
            #pragma unroll
            for (int g2 = 0; g2 < 16; g2++) { s1 += red1[g2][lane]; s2 += red2[g2][lane]; }
            float mean = s1 * (1.f / BATCH);
            float var = s2 * (1.f / BATCH) - mean * mean;
            smean[slot_t][lane] = mean;
            srstd[slot_t][lane] = rsqrtf(var + BN_EPS);
        }
        __syncthreads();
        // --- normalize in place (+ export bf16 split for banks 14/15) ---
        {
            float m = smean[slot_t][nd], r = srstd[slot_t][nd];
            float4 vv = *(float4*)&actT[slot_t][nd][nrg];
            vv.x = (vv.x - m) * r; vv.y = (vv.y - m) * r;
            vv.z = (vv.z - m) * r; vv.w = (vv.w - m) * r;
            *(float4*)&actT[slot_t][nd][nrg] = vv;
            if (t >= 14) {
                int krow = (t - 14) * 32 + nd;
                uint2 hv, lv;
                hv.x = pack_hi2(vv.x, vv.y); hv.y = pack_hi2(vv.z, vv.w);
                lv.x = pack_lo2(vv.x, vv.y); lv.y = pack_lo2(vv.z, vv.w);
                *(uint2*)&g_preTH[krow * BATCH + rowBase + nrg] = hv;
                *(uint2*)&g_preTL[krow * BATCH + rowBase + nrg] = lv;
            }
        }
        __syncthreads();
    }
    if (tid < 64) tg[rowBase + tid] = stg[tid];
}

// ---------------- output GEMM (unchanged) ----------------
#define ATM 72
#define AST 72
__global__ void __launch_bounds__(256) gemm_out_tc(float* __restrict__ out) {
    __shared__ __nv_bfloat16 ATh[64 * ATM];
    __shared__ __nv_bfloat16 ATl[64 * ATM];
    __shared__ __nv_bfloat16 Bh[64 * AST];
    __shared__ __nv_bfloat16 Bl[64 * AST];
    int tid = threadIdx.x;
    int w = tid >> 5, l = tid & 31;
    int wm = w & 3, wn = w >> 2;
    int rowBase = blockIdx.x * 64;
    int colBase = blockIdx.y * 64;
    unsigned ah_b = smem_u32(ATh), al_b = smem_u32(ATl);
    unsigned bh_b = smem_u32(Bh), bl_b = smem_u32(Bl);

    #pragma unroll
    for (int p = 0; p < 2; p++) {
        int idx = p * 256 + tid;
        int k = idx >> 3;
        int m8 = (idx & 7) * 8;
        *(uint4*)&ATh[k * ATM + m8] = *(const uint4*)&g_preTH[k * BATCH + rowBase + m8];
        *(uint4*)&ATl[k * ATM + m8] = *(const uint4*)&g_preTL[k * BATCH + rowBase + m8];
    }
    #pragma unroll
    for (int p = 0; p < 2; p++) {
        int idx = p * 256 + tid;
        int k = idx >> 3;
        int n8 = (idx & 7) * 8;
        *(uint4*)&Bh[k * AST + n8] = *(const uint4*)&g_WoutH[k * 1024 + colBase + n8];
        *(uint4*)&Bl[k * AST + n8] = *(const uint4*)&g_WoutL[k * 1024 + colBase + n8];
    }
    __syncthreads();

    float c[4][4];
    #pragma unroll
    for (int i = 0; i < 4; i++)
        #pragma unroll
        for (int j = 0; j < 4; j++) c[i][j] = 0.f;

    int a_k = (l & 7) + (l >> 4) * 8;
    int a_m = wm * 16 + ((l >> 3) & 1) * 8;
    int b_k = (l & 7) + ((l >> 3) & 1) * 8;
    int b_n = (l >> 4) * 8;

    #pragma unroll
    for (int ks = 0; ks < 4; ks++) {
        int k0 = ks * 16;
        unsigned a_off = (unsigned)((k0 + a_k) * (ATM * 2) + a_m * 2);
        unsigned ah[4], al[4];
        ldsm_x4_t(ah[0], ah[1], ah[2], ah[3], ah_b + a_off);
        ldsm_x4_t(al[0], al[1], al[2], al[3], al_b + a_off);
        #pragma unroll
        for (int g = 0; g < 2; g++) {
            int n0 = wn * 32 + g * 16;
            unsigned b_off = (unsigned)((k0 + b_k) * (AST * 2) + (n0 + b_n) * 2);
            unsigned h0, h1, h2, h3, q0, q1, q2, q3;
            ldsm_x4_t(h0, h1, h2, h3, bh_b + b_off);
            ldsm_x4_t(q0, q1, q2, q3, bl_b + b_off);
            mma_bf16(c[2 * g],     ah, h0, h1);
            mma_bf16(c[2 * g + 1], ah, h2, h3);
            mma_bf16(c[2 * g],     ah, q0, q1);
            mma_bf16(c[2 * g + 1], ah, q2, q3);
            mma_bf16(c[2 * g],     al, h0, h1);
            mma_bf16(c[2 * g + 1], al, h2, h3);
        }
    }
    int r0 = rowBase + wm * 16 + (l >> 2);
    #pragma unroll
    for (int nb = 0; nb < 4; nb++) {
        int col = colBase + wn * 32 + nb * 8 + (l & 3) * 2;
        if (col < NOUT) {
            float2 v0 = make_float2(c[nb][0], c[nb][1]);
            float2 v1 = make_float2(c[nb][2], c[nb][3]);
            *(float2*)&out[(size_t)r0 * NOUT + col] = v0;
            *(float2*)&out[(size_t)(r0 + 8) * NOUT + col] = v1;
        }
    }
}

// ---------------- launch ----------------
extern "C" void kernel_launch(void* const* d_in, const int* in_sizes, int n_in,
                              void* d_out, int out_size) {
    const float* x     = (const float*)d_in[0];
    const float* gamma = (const float*)d_in[1];
    const float* beta  = (const float*)d_in[2];
    const float* W_in  = (const float*)d_in[3];
    const float* b_in  = (const float*)d_in[4];
    const float* Wg    = (const float*)d_in[5];
    const float* Wd    = (const float*)d_in[6];
    const float* bd    = (const float*)d_in[7];
    const float* Wout  = (const float*)d_in[8];
    float* out = (float*)d_out;

    float* tg;
    if (out_size >= BATCH * NOUT + BATCH) {
        tg = out + (size_t)BATCH * NOUT;
    } else {
        void* p = nullptr;
        cudaGetSymbolAddress(&p, g_tg_fallback);
        tg = (float*)p;
    }

    prep_kernel<<<PB, 256>>>(x, gamma, beta, W_in, b_in);
    woutfold_kernel<<<4, 256>>>(Wout);
    gemm_in_tc<<<128, 256>>>(x);
    chain_kernel<<<CB, 512>>>(Wg, Wd, bd, tg);   // 4th launch -> ncu target
    gemm_out_tc<<<dim3(128, 16), 256>>>(out);
}

// round 9
// speedup vs baseline: 4.1231x; 1.0417x over previous
#include <cuda_runtime.h>
#include <cuda_bf16.h>
#include <stdint.h>
#include <math.h>

#define NBANKS 16
#define D 32
#define NIN 3072
#define NOUT 1000
#define BATCH 8192
#define BN_EPS 1e-5f
#define CB 128
#define PB 128

// ---------------- device scratch ----------------
__device__ float g_px1[PB * NIN];
__device__ float g_px2[PB * NIN];
__device__ float g_scale[NIN];
__device__ float g_shift[NIN];
__device__ float g_bpart[PB * 64];
__device__ __nv_bfloat16 g_WpH[NIN * 64];
__device__ __nv_bfloat16 g_WpL[NIN * 64];
__device__ float g_bp[64];
__device__ float g_in0[BATCH * D];
__device__ float g_in1[BATCH * D];
__device__ __nv_bfloat16 g_preTH[64 * BATCH];
__device__ __nv_bfloat16 g_preTL[64 * BATCH];
__device__ __nv_bfloat16 g_WoutH[64 * 1024];
__device__ __nv_bfloat16 g_WoutL[64 * 1024];
__device__ float g_p1s[NBANKS * CB * 32];
__device__ float g_p2s[NBANKS * CB * 32];
__device__ unsigned g_barc;
__device__ unsigned g_barg;
__device__ float g_tg_fallback[BATCH];

// ---------------- helpers ----------------
__device__ __forceinline__ unsigned smem_u32(const void* p) {
    return (unsigned)__cvta_generic_to_shared(p);
}
__device__ __forceinline__ void ldsm_x4(unsigned& r0, unsigned& r1, unsigned& r2,
                                        unsigned& r3, unsigned addr) {
    asm volatile("ldmatrix.sync.aligned.m8n8.x4.shared.b16 {%0,%1,%2,%3},[%4];"
                 : "=r"(r0), "=r"(r1), "=r"(r2), "=r"(r3) : "r"(addr));
}
__device__ __forceinline__ void ldsm_x4_t(unsigned& r0, unsigned& r1, unsigned& r2,
                                          unsigned& r3, unsigned addr) {
    asm volatile("ldmatrix.sync.aligned.m8n8.x4.trans.shared.b16 {%0,%1,%2,%3},[%4];"
                 : "=r"(r0), "=r"(r1), "=r"(r2), "=r"(r3) : "r"(addr));
}
__device__ __forceinline__ void mma_bf16(float* c, const unsigned* a,
                                         unsigned b0, unsigned b1) {
    asm volatile(
        "mma.sync.aligned.m16n8k16.row.col.f32.bf16.bf16.f32 "
        "{%0,%1,%2,%3},{%4,%5,%6,%7},{%8,%9},{%0,%1,%2,%3};"
        : "+f"(c[0]), "+f"(c[1]), "+f"(c[2]), "+f"(c[3])
        : "r"(a[0]), "r"(a[1]), "r"(a[2]), "r"(a[3]), "r"(b0), "r"(b1));
}
__device__ __forceinline__ unsigned pack_hi2(float x, float y) {
    __nv_bfloat16 hx = __float2bfloat16(x), hy = __float2bfloat16(y);
    return ((unsigned)__bfloat16_as_ushort(hy) << 16) | __bfloat16_as_ushort(hx);
}
__device__ __forceinline__ unsigned pack_lo2(float x, float y) {
    __nv_bfloat16 hx = __float2bfloat16(x), hy = __float2bfloat16(y);
    float lx = x - __bfloat162float(hx), ly = y - __bfloat162float(hy);
    __nv_bfloat16 bx = __float2bfloat16(lx), by = __float2bfloat16(ly);
    return ((unsigned)__bfloat16_as_ushort(by) << 16) | __bfloat16_as_ushort(bx);
}

// ---------------- grid barrier (monolithic form, used by prep) -------------
__device__ __forceinline__ void grid_bar_n(int nblk) {
    __syncthreads();
    if (threadIdx.x == 0) {
        unsigned gen = *(volatile unsigned*)&g_barg;
        __threadfence();
        if (atomicAdd(&g_barc, 1u) == (unsigned)nblk - 1) {
            atomicExch(&g_barc, 0u);
            __threadfence();
            *(volatile unsigned*)&g_barg = gen + 1;
        } else {
            while (*(volatile unsigned*)&g_barg == gen) { }
        }
        __threadfence();
    }
    __syncthreads();
}

// ---------------- fused prep (unchanged) ----------------
__global__ void __launch_bounds__(256, 1) prep_kernel(
    const float* __restrict__ x, const float* __restrict__ gamma,
    const float* __restrict__ beta, const float* __restrict__ W_in,
    const float* __restrict__ b_in) {
    int tid = threadIdx.x;
    int blk = blockIdx.x;
    int warp = tid >> 5, lane = tid & 31;

    {
        float s1[3][4], s2[3][4];
        #pragma unroll
        for (int g = 0; g < 3; g++)
            #pragma unroll
            for (int i = 0; i < 4; i++) { s1[g][i] = 0.f; s2[g][i] = 0.f; }
        int row0 = blk * 64;
        for (int r = 0; r < 64; r++) {
            const float* xr = x + (size_t)(row0 + r) * NIN;
            #pragma unroll
            for (int g = 0; g < 3; g++) {
                float4 v = *(const float4*)&xr[g * 1024 + tid * 4];
                s1[g][0] += v.x; s2[g][0] += v.x * v.x;
                s1[g][1] += v.y; s2[g][1] += v.y * v.y;
                s1[g][2] += v.z; s2[g][2] += v.z * v.z;
                s1[g][3] += v.w; s2[g][3] += v.w * v.w;
            }
        }
        #pragma unroll
        for (int g = 0; g < 3; g++) {
            *(float4*)&g_px1[blk * NIN + g * 1024 + tid * 4] =
                make_float4(s1[g][0], s1[g][1], s1[g][2], s1[g][3]);
            *(float4*)&g_px2[blk * NIN + g * 1024 + tid * 4] =
                make_float4(s2[g][0], s2[g][1], s2[g][2], s2[g][3]);
        }
    }
    grid_bar_n(PB);
    {
        #pragma unroll
        for (int cc = 0; cc < 3; cc++) {
            int col = blk * 24 + warp * 3 + cc;
            float a = 0.f, b = 0.f;
            #pragma unroll
            for (int q = 0; q < 4; q++) {
                a += g_px1[(lane + q * 32) * NIN + col];
                b += g_px2[(lane + q * 32) * NIN + col];
            }
            #pragma unroll
            for (int o = 16; o; o >>= 1) {
                a += __shfl_xor_sync(~0u, a, o);
                b += __shfl_xor_sync(~0u, b, o);
            }
            if (lane == 0) {
                float mean = a * (1.f / BATCH);
                float var = b * (1.f / BATCH) - mean * mean;
                float rstd = rsqrtf(var + BN_EPS);
                float sc = rstd * gamma[col];
                g_scale[col] = sc;
                g_shift[col] = beta[col] - mean * sc;
            }
        }
    }
    grid_bar_n(PB);
    {
        __shared__ float sred[4][64];
        int j = tid & 63, grp = tid >> 6;
        int k = j >> 5, d = j & 31;
        float bias = 0.f;
        #pragma unroll
        for (int p = 0; p < 6; p++) {
            int c = blk * 24 + grp * 6 + p;
            float wraw = W_in[(size_t)k * NIN * D + c * D + d];
            float w = g_scale[c] * wraw;
            __nv_bfloat16 h = __float2bfloat16(w);
            g_WpH[c * 64 + j] = h;
            g_WpL[c * 64 + j] = __float2bfloat16(w - __bfloat162float(h));
            bias += g_shift[c] * wraw;
        }
        sred[grp][j] = bias;
        __syncthreads();
        if (tid < 64)
            g_bpart[blk * 64 + tid] =
                sred[0][tid] + sred[1][tid] + sred[2][tid] + sred[3][tid];
    }
    grid_bar_n(PB);
    if (blk == 0) {
        __shared__ float sred2[4][64];
        int j = tid & 63, grp = tid >> 6;
        float s = 0.f;
        #pragma unroll 8
        for (int b = grp; b < PB; b += 4) s += g_bpart[b * 64 + j];
        sred2[grp][j] = s;
        __syncthreads();
        if (tid < 64)
            g_bp[tid] = b_in[tid] +
                sred2[0][tid] + sred2[1][tid] + sred2[2][tid] + sred2[3][tid];
    }
}

__global__ void woutfold_kernel(const float* __restrict__ Wout) {
    int n = blockIdx.x * 256 + threadIdx.x;
    #pragma unroll 8
    for (int k = 0; k < 64; k++) {
        int bank = k >> 5, d = k & 31;
        float w = (n < NOUT) ? Wout[(size_t)bank * D * NOUT + d * NOUT + n] : 0.f;
        __nv_bfloat16 h = __float2bfloat16(w);
        g_WoutH[k * 1024 + n] = h;
        g_WoutL[k * 1024 + n] = __float2bfloat16(w - __bfloat162float(h));
    }
}

// ---------------- input GEMM (unchanged) ----------------
#define APAD 40
#define BPAD 72
__global__ void __launch_bounds__(256) gemm_in_tc(const float* __restrict__ x) {
    __shared__ __nv_bfloat16 Ah[2][64 * APAD];
    __shared__ __nv_bfloat16 Al[2][64 * APAD];
    __shared__ __nv_bfloat16 Bh[2][32 * BPAD];
    __shared__ __nv_bfloat16 Bl[2][32 * BPAD];
    int tid = threadIdx.x;
    int w = tid >> 5, l = tid & 31;
    int wm = w & 3, wn = w >> 2;
    int rowBase = blockIdx.x * 64;

    int a_r0 = tid >> 3;
    int a_k4 = (tid & 7) * 4;
    int b_kk = tid >> 3;
    int b_n8 = (tid & 7) * 8;

    float4 pa0, pa1;
    uint4 pbh, pbl;
    pa0 = *(const float4*)&x[(size_t)(rowBase + a_r0) * NIN + a_k4];
    pa1 = *(const float4*)&x[(size_t)(rowBase + a_r0 + 32) * NIN + a_k4];
    pbh = *(const uint4*)&g_WpH[b_kk * 64 + b_n8];
    pbl = *(const uint4*)&g_WpL[b_kk * 64 + b_n8];
    {
        uint2 h0, l0;
        h0.x = pack_hi2(pa0.x, pa0.y); h0.y = pack_hi2(pa0.z, pa0.w);
        l0.x = pack_lo2(pa0.x, pa0.y); l0.y = pack_lo2(pa0.z, pa0.w);
        *(uint2*)&Ah[0][a_r0 * APAD + a_k4] = h0;
        *(uint2*)&Al[0][a_r0 * APAD + a_k4] = l0;
        h0.x = pack_hi2(pa1.x, pa1.y); h0.y = pack_hi2(pa1.z, pa1.w);
        l0.x = pack_lo2(pa1.x, pa1.y); l0.y = pack_lo2(pa1.z, pa1.w);
        *(uint2*)&Ah[0][(a_r0 + 32) * APAD + a_k4] = h0;
        *(uint2*)&Al[0][(a_r0 + 32) * APAD + a_k4] = l0;
        *(uint4*)&Bh[0][b_kk * BPAD + b_n8] = pbh;
        *(uint4*)&Bl[0][b_kk * BPAD + b_n8] = pbl;
    }
    __syncthreads();

    float c[4][4];
    #pragma unroll
    for (int i = 0; i < 4; i++)
        #pragma unroll
        for (int j = 0; j < 4; j++) c[i][j] = 0.f;

    int a_row = wm * 16 + (l & 7) + ((l >> 3) & 1) * 8;
    int a_kof = (l >> 4) * 8;
    int b_k = (l & 7) + ((l >> 3) & 1) * 8;
    int b_n = (l >> 4) * 8;

    for (int kt = 0; kt < 96; kt++) {
        int cur = kt & 1, nxt = cur ^ 1;
        if (kt < 95) {
            int kb = (kt + 1) * 32;
            pa0 = *(const float4*)&x[(size_t)(rowBase + a_r0) * NIN + kb + a_k4];
            pa1 = *(const float4*)&x[(size_t)(rowBase + a_r0 + 32) * NIN + kb + a_k4];
            pbh = *(const uint4*)&g_WpH[(kb + b_kk) * 64 + b_n8];
            pbl = *(const uint4*)&g_WpL[(kb + b_kk) * 64 + b_n8];
        }
        unsigned ahb = smem_u32(Ah[cur]), alb = smem_u32(Al[cur]);
        unsigned bhb = smem_u32(Bh[cur]), blb = smem_u32(Bl[cur]);
        #pragma unroll
        for (int ks = 0; ks < 2; ks++) {
            int k0 = ks * 16;
            unsigned a_off = (unsigned)(a_row * (APAD * 2) + (k0 + a_kof) * 2);
            unsigned ah[4], al[4];
            ldsm_x4(ah[0], ah[1], ah[2], ah[3], ahb + a_off);
            ldsm_x4(al[0], al[1], al[2], al[3], alb + a_off);
            #pragma unroll
            for (int g = 0; g < 2; g++) {
                int n0 = wn * 32 + g * 16;
                unsigned b_off = (unsigned)((k0 + b_k) * (BPAD * 2) + (n0 + b_n) * 2);
                unsigned h0, h1, h2, h3, q0, q1, q2, q3;
                ldsm_x4_t(h0, h1, h2, h3, bhb + b_off);
                ldsm_x4_t(q0, q1, q2, q3, blb + b_off);
                mma_bf16(c[2 * g],     ah, h0, h1);
                mma_bf16(c[2 * g + 1], ah, h2, h3);
                mma_bf16(c[2 * g],     ah, q0, q1);
                mma_bf16(c[2 * g + 1], ah, q2, q3);
                mma_bf16(c[2 * g],     al, h0, h1);
                mma_bf16(c[2 * g + 1], al, h2, h3);
            }
        }
        if (kt < 95) {
            uint2 h0, l0;
            h0.x = pack_hi2(pa0.x, pa0.y); h0.y = pack_hi2(pa0.z, pa0.w);
            l0.x = pack_lo2(pa0.x, pa0.y); l0.y = pack_lo2(pa0.z, pa0.w);
            *(uint2*)&Ah[nxt][a_r0 * APAD + a_k4] = h0;
            *(uint2*)&Al[nxt][a_r0 * APAD + a_k4] = l0;
            h0.x = pack_hi2(pa1.x, pa1.y); h0.y = pack_hi2(pa1.z, pa1.w);
            l0.x = pack_lo2(pa1.x, pa1.y); l0.y = pack_lo2(pa1.z, pa1.w);
            *(uint2*)&Ah[nxt][(a_r0 + 32) * APAD + a_k4] = h0;
            *(uint2*)&Al[nxt][(a_r0 + 32) * APAD + a_k4] = l0;
            *(uint4*)&Bh[nxt][b_kk * BPAD + b_n8] = pbh;
            *(uint4*)&Bl[nxt][b_kk * BPAD + b_n8] = pbl;
        }
        __syncthreads();
    }
    int r0 = rowBase + wm * 16 + (l >> 2);
    #pragma unroll
    for (int nb = 0; nb < 4; nb++) {
        int col = wn * 32 + nb * 8 + (l & 3) * 2;
        float2 bp = *(const float2*)&g_bp[col];
        float2 v0, v1;
        v0.x = fmaxf(c[nb][0] + bp.x, 0.f);
        v0.y = fmaxf(c[nb][1] + bp.y, 0.f);
        v1.x = fmaxf(c[nb][2] + bp.x, 0.f);
        v1.y = fmaxf(c[nb][3] + bp.y, 0.f);
        if (col < 32) {
            *(float2*)&g_in0[r0 * D + col] = v0;
            *(float2*)&g_in0[(r0 + 8) * D + col] = v1;
        } else {
            *(float2*)&g_in1[r0 * D + col - 32] = v0;
            *(float2*)&g_in1[(r0 + 8) * D + col - 32] = v1;
        }
    }
}

// ---------------- pipelined bank-chain kernel, 512 threads -----------------
// Per thread: 2 rows (r0, r0+1) x 2 cols (j0, j0+1). Gate computed in the
// data loop (each thread computes its own rows' gates). Early edges overlap
// the grid-barrier wait; only the late edge (freshly normalized source) is
// on the post-barrier critical path.
#define EDGE_ACC(E, SLOT)                                                     \
    do {                                                                      \
        const float* wp = Wd + (E) * 1024 + j0;                               \
        const float* wgp = Wg + (E) * 32;                                     \
        float2 b2 = __ldg((const float2*)&bd[(E) * 32 + j0]);                 \
        float d00 = b2.x, d01 = b2.y, d10 = b2.x, d11 = b2.y;                 \
        float g0 = 0.f, g1 = 0.f;                                             \
        _Pragma("unroll")                                                     \
        for (int k = 0; k < 32; k++) {                                        \
            float2 a2 = *(const float2*)&actT[(SLOT)][k][r0];                 \
            float2 w2 = __ldg((const float2*)&wp[k * 32]);                    \
            float wgk = __ldg(&wgp[k]);                                       \
            d00 += a2.x * w2.x; d01 += a2.x * w2.y;                           \
            d10 += a2.y * w2.x; d11 += a2.y * w2.y;                           \
            g0 += a2.x * wgk; g1 += a2.y * wgk;                               \
        }                                                                     \
        g0 = fminf(fmaxf(g0, 0.f), 1.f);                                      \
        g1 = fminf(fmaxf(g1, 0.f), 1.f);                                      \
        if ((tid & 15) == 0) { stg[r0] += g0; stg[r0 + 1] += g1; }            \
        n00 += g0 * d00; n01 += g0 * d01;                                     \
        n10 += g1 * d10; n11 += g1 * d11;                                     \
    } while (0)

__global__ void __launch_bounds__(512, 1) chain_kernel(
    const float* __restrict__ Wg, const float* __restrict__ Wd,
    const float* __restrict__ bd, float* __restrict__ tg) {
    __shared__ __align__(16) float actT[4][32][68];
    __shared__ float stg[64];
    __shared__ float smean[32], srstd[32];
    __shared__ float red1[16][32], red2[16][32];

    int tid = threadIdx.x;
    int blk = blockIdx.x;
    int rowBase = blk * 64;
    int j0 = (tid & 15) * 2;
    int r0 = (tid >> 4) * 2;
    int warp = tid >> 5, lane = tid & 31;
    int nd = tid >> 4, nrg = (tid & 15) * 4;
    if (tid < 64) stg[tid] = 0.f;

    float acc00, acc01, acc10, acc11;
    {
        float2 v0 = *(const float2*)&g_in0[(rowBase + r0) * D + j0];
        float2 v1 = *(const float2*)&g_in0[(rowBase + r0 + 1) * D + j0];
        acc00 = v0.x; acc01 = v0.y; acc10 = v1.x; acc11 = v1.y;
    }
    __syncthreads();

    for (int t = 0; t < 16; t++) {
        int slot_t = t & 3;
        // 1. relu + store + warp-shuffle stats partials
        float v00 = fmaxf(acc00, 0.f), v01 = fmaxf(acc01, 0.f);
        float v10 = fmaxf(acc10, 0.f), v11 = fmaxf(acc11, 0.f);
        *(float2*)&actT[slot_t][j0][r0]     = make_float2(v00, v10);
        *(float2*)&actT[slot_t][j0 + 1][r0] = make_float2(v01, v11);
        float s1a = v00 + v10, s1b = v01 + v11;
        float s2a = v00 * v00 + v10 * v10, s2b = v01 * v01 + v11 * v11;
        s1a += __shfl_xor_sync(~0u, s1a, 16);
        s1b += __shfl_xor_sync(~0u, s1b, 16);
        s2a += __shfl_xor_sync(~0u, s2a, 16);
        s2b += __shfl_xor_sync(~0u, s2b, 16);
        if (lane < 16) {
            red1[warp][j0] = s1a; red1[warp][j0 + 1] = s1b;
            red2[warp][j0] = s2a; red2[warp][j0 + 1] = s2b;
        }
        __syncthreads();
        if (warp == 0) {
            float s1 = 0.f, s2 = 0.f;
            #pragma unroll
            for (int g = 0; g < 16; g++) { s1 += red1[g][lane]; s2 += red2[g][lane]; }
            g_p1s[(t * CB + blk) * 32 + lane] = s1;
            g_p2s[(t * CB + blk) * 32 + lane] = s2;
        }
        __syncthreads();
        // 2. barrier ARRIVE (thread 0), then everyone does early-edge work
        unsigned gen = 0;
        if (tid == 0) {
            gen = *(volatile unsigned*)&g_barg;
            __threadfence();
            if (atomicAdd(&g_barc, 1u) == CB - 1) {
                atomicExch(&g_barc, 0u);
                __threadfence();
                *(volatile unsigned*)&g_barg = gen + 1;
            }
        }
        // 3. EARLY edges for bank tt=t+1 (sources already normalized)
        int tt = t + 1;
        float n00 = 0.f, n01 = 0.f, n10 = 0.f, n11 = 0.f;
        int tec = 0, teb = 0, ts0 = 0;
        if (tt < 16) {
            if (tt == 1) {
                float2 v0 = *(const float2*)&g_in1[(rowBase + r0) * D + j0];
                float2 v1 = *(const float2*)&g_in1[(rowBase + r0 + 1) * D + j0];
                n00 = v0.x; n01 = v0.y; n10 = v1.x; n11 = v1.y;
            }
            tec = (tt < 4) ? tt : 4;
            ts0 = (tt - 4 < 0) ? 0 : tt - 4;
            teb = (tt <= 1) ? 0 : (tt == 2) ? 1 : (tt == 3) ? 3 : (tt == 4) ? 6
                                : 10 + (tt - 5) * 4;
            for (int ei = 0; ei < tec - 1; ei++) {
                int e = teb + ei, slot = (ts0 + ei) & 3;
                EDGE_ACC(e, slot);
            }
        }
        // 4. barrier WAIT
        if (tid == 0) {
            while (*(volatile unsigned*)&g_barg == gen) { }
            __threadfence();
        }
        __syncthreads();
        // 5. finalize stats for bank t
        {
            float s1 = 0.f, s2 = 0.f;
            #pragma unroll
            for (int q = 0; q < 8; q++) {
                int b = warp + q * 16;
                s1 += __ldcg(&g_p1s[(t * CB + b) * 32 + lane]);
                s2 += __ldcg(&g_p2s[(t * CB + b) * 32 + lane]);
            }
            red1[warp][lane] = s1;
            red2[warp][lane] = s2;
        }
        __syncthreads();
        if (warp == 0) {
            float s1 = 0.f, s2 = 0.f;
            #pragma unroll
            for (int g = 0; g < 16; g++) { s1 += red1[g][lane]; s2 += red2[g][lane]; }
            float mean = s1 * (1.f / BATCH);
            float var = s2 * (1.f / BATCH) - mean * mean;
            smean[lane] = mean;
            srstd[lane] = rsqrtf(var + BN_EPS);
        }
        __syncthreads();
        // 6. normalize slot_t in place (+ export bf16 for banks 14/15)
        {
            float m = smean[nd], r = srstd[nd];
            float4 vv = *(float4*)&actT[slot_t][nd][nrg];
            vv.x = (vv.x - m) * r; vv.y = (vv.y - m) * r;
            vv.z = (vv.z - m) * r; vv.w = (vv.w - m) * r;
            *(float4*)&actT[slot_t][nd][nrg] = vv;
            if (t >= 14) {
                int krow = (t - 14) * 32 + nd;
                uint2 hv, lv;
                hv.x = pack_hi2(vv.x, vv.y); hv.y = pack_hi2(vv.z, vv.w);
                lv.x = pack_lo2(vv.x, vv.y); lv.y = pack_lo2(vv.z, vv.w);
                *(uint2*)&g_preTH[krow * BATCH + rowBase + nrg] = hv;
                *(uint2*)&g_preTL[krow * BATCH + rowBase + nrg] = lv;
            }
        }
        __syncthreads();
        // 7. LATE edge (source t, just normalized)
        if (tt < 16) {
            int e = teb + tec - 1;
            EDGE_ACC(e, slot_t);
        }
        acc00 = n00; acc01 = n01; acc10 = n10; acc11 = n11;
    }
    __syncthreads();
    if (tid < 64) tg[rowBase + tid] = stg[tid];
}

// ---------------- output GEMM (unchanged) ----------------
#define ATM 72
#define AST 72
__global__ void __launch_bounds__(256) gemm_out_tc(float* __restrict__ out) {
    __shared__ __nv_bfloat16 ATh[64 * ATM];
    __shared__ __nv_bfloat16 ATl[64 * ATM];
    __shared__ __nv_bfloat16 Bh[64 * AST];
    __shared__ __nv_bfloat16 Bl[64 * AST];
    int tid = threadIdx.x;
    int w = tid >> 5, l = tid & 31;
    int wm = w & 3, wn = w >> 2;
    int rowBase = blockIdx.x * 64;
    int colBase = blockIdx.y * 64;
    unsigned ah_b = smem_u32(ATh), al_b = smem_u32(ATl);
    unsigned bh_b = smem_u32(Bh), bl_b = smem_u32(Bl);

    #pragma unroll
    for (int p = 0; p < 2; p++) {
        int idx = p * 256 + tid;
        int k = idx >> 3;
        int m8 = (idx & 7) * 8;
        *(uint4*)&ATh[k * ATM + m8] = *(const uint4*)&g_preTH[k * BATCH + rowBase + m8];
        *(uint4*)&ATl[k * ATM + m8] = *(const uint4*)&g_preTL[k * BATCH + rowBase + m8];
    }
    #pragma unroll
    for (int p = 0; p < 2; p++) {
        int idx = p * 256 + tid;
        int k = idx >> 3;
        int n8 = (idx & 7) * 8;
        *(uint4*)&Bh[k * AST + n8] = *(const uint4*)&g_WoutH[k * 1024 + colBase + n8];
        *(uint4*)&Bl[k * AST + n8] = *(const uint4*)&g_WoutL[k * 1024 + colBase + n8];
    }
    __syncthreads();

    float c[4][4];
    #pragma unroll
    for (int i = 0; i < 4; i++)
        #pragma unroll
        for (int j = 0; j < 4; j++) c[i][j] = 0.f;

    int a_k = (l & 7) + (l >> 4) * 8;
    int a_m = wm * 16 + ((l >> 3) & 1) * 8;
    int b_k = (l & 7) + ((l >> 3) & 1) * 8;
    int b_n = (l >> 4) * 8;

    #pragma unroll
    for (int ks = 0; ks < 4; ks++) {
        int k0 = ks * 16;
        unsigned a_off = (unsigned)((k0 + a_k) * (ATM * 2) + a_m * 2);
        unsigned ah[4], al[4];
        ldsm_x4_t(ah[0], ah[1], ah[2], ah[3], ah_b + a_off);
        ldsm_x4_t(al[0], al[1], al[2], al[3], al_b + a_off);
        #pragma unroll
        for (int g = 0; g < 2; g++) {
            int n0 = wn * 32 + g * 16;
            unsigned b_off = (unsigned)((k0 + b_k) * (AST * 2) + (n0 + b_n) * 2);
            unsigned h0, h1, h2, h3, q0, q1, q2, q3;
            ldsm_x4_t(h0, h1, h2, h3, bh_b + b_off);
            ldsm_x4_t(q0, q1, q2, q3, bl_b + b_off);
            mma_bf16(c[2 * g],     ah, h0, h1);
            mma_bf16(c[2 * g + 1], ah, h2, h3);
            mma_bf16(c[2 * g],     ah, q0, q1);
            mma_bf16(c[2 * g + 1], ah, q2, q3);
            mma_bf16(c[2 * g],     al, h0, h1);
            mma_bf16(c[2 * g + 1], al, h2, h3);
        }
    }
    int r0 = rowBase + wm * 16 + (l >> 2);
    #pragma unroll
    for (int nb = 0; nb < 4; nb++) {
        int col = colBase + wn * 32 + nb * 8 + (l & 3) * 2;
        if (col < NOUT) {
            float2 v0 = make_float2(c[nb][0], c[nb][1]);
            float2 v1 = make_float2(c[nb][2], c[nb][3]);
            *(float2*)&out[(size_t)r0 * NOUT + col] = v0;
            *(float2*)&out[(size_t)(r0 + 8) * NOUT + col] = v1;
        }
    }
}

// ---------------- launch ----------------
extern "C" void kernel_launch(void* const* d_in, const int* in_sizes, int n_in,
                              void* d_out, int out_size) {
    const float* x     = (const float*)d_in[0];
    const float* gamma = (const float*)d_in[1];
    const float* beta  = (const float*)d_in[2];
    const float* W_in  = (const float*)d_in[3];
    const float* b_in  = (const float*)d_in[4];
    const float* Wg    = (const float*)d_in[5];
    const float* Wd    = (const float*)d_in[6];
    const float* bd    = (const float*)d_in[7];
    const float* Wout  = (const float*)d_in[8];
    float* out = (float*)d_out;

    float* tg;
    if (out_size >= BATCH * NOUT + BATCH) {
        tg = out + (size_t)BATCH * NOUT;
    } else {
        void* p = nullptr;
        cudaGetSymbolAddress(&p, g_tg_fallback);
        tg = (float*)p;
    }

    prep_kernel<<<PB, 256>>>(x, gamma, beta, W_in, b_in);
    woutfold_kernel<<<4, 256>>>(Wout);
    gemm_in_tc<<<128, 256>>>(x);
    chain_kernel<<<CB, 512>>>(Wg, Wd, bd, tg);   // 4th launch -> ncu target
    gemm_out_tc<<<dim3(128, 16), 256>>>(out);
}

// round 10
// speedup vs baseline: 4.1283x; 1.0013x over previous
#include <cuda_runtime.h>
#include <cuda_bf16.h>
#include <stdint.h>
#include <math.h>

#define NBANKS 16
#define D 32
#define NIN 3072
#define NOUT 1000
#define BATCH 8192
#define BN_EPS 1e-5f
#define CB 128
#define PB 128

// ---------------- device scratch ----------------
__device__ float g_px1[PB * NIN];
__device__ float g_px2[PB * NIN];
__device__ float g_scale[NIN];
__device__ float g_shift[NIN];
__device__ float g_bpart[PB * 64];
__device__ __nv_bfloat16 g_WpH[NIN * 64];
__device__ __nv_bfloat16 g_WpL[NIN * 64];
__device__ float g_bp[64];
__device__ float g_in0[BATCH * D];
__device__ float g_in1[BATCH * D];
__device__ __nv_bfloat16 g_preTH[64 * BATCH];
__device__ __nv_bfloat16 g_preTL[64 * BATCH];
__device__ __nv_bfloat16 g_WoutH[64 * 1024];
__device__ __nv_bfloat16 g_WoutL[64 * 1024];
__device__ float g_p1s[NBANKS * CB * 32];
__device__ float g_p2s[NBANKS * CB * 32];
__device__ unsigned g_barc;
__device__ unsigned g_barg;
__device__ unsigned g_cflag[CB];   // chain per-block arrival flags
__device__ unsigned g_cgen;        // chain release word
__device__ float g_tg_fallback[BATCH];

// ---------------- helpers ----------------
__device__ __forceinline__ unsigned smem_u32(const void* p) {
    return (unsigned)__cvta_generic_to_shared(p);
}
__device__ __forceinline__ void ldsm_x4(unsigned& r0, unsigned& r1, unsigned& r2,
                                        unsigned& r3, unsigned addr) {
    asm volatile("ldmatrix.sync.aligned.m8n8.x4.shared.b16 {%0,%1,%2,%3},[%4];"
                 : "=r"(r0), "=r"(r1), "=r"(r2), "=r"(r3) : "r"(addr));
}
__device__ __forceinline__ void ldsm_x4_t(unsigned& r0, unsigned& r1, unsigned& r2,
                                          unsigned& r3, unsigned addr) {
    asm volatile("ldmatrix.sync.aligned.m8n8.x4.trans.shared.b16 {%0,%1,%2,%3},[%4];"
                 : "=r"(r0), "=r"(r1), "=r"(r2), "=r"(r3) : "r"(addr));
}
__device__ __forceinline__ void mma_bf16(float* c, const unsigned* a,
                                         unsigned b0, unsigned b1) {
    asm volatile(
        "mma.sync.aligned.m16n8k16.row.col.f32.bf16.bf16.f32 "
        "{%0,%1,%2,%3},{%4,%5,%6,%7},{%8,%9},{%0,%1,%2,%3};"
        : "+f"(c[0]), "+f"(c[1]), "+f"(c[2]), "+f"(c[3])
        : "r"(a[0]), "r"(a[1]), "r"(a[2]), "r"(a[3]), "r"(b0), "r"(b1));
}
__device__ __forceinline__ unsigned pack_hi2(float x, float y) {
    __nv_bfloat16 hx = __float2bfloat16(x), hy = __float2bfloat16(y);
    return ((unsigned)__bfloat16_as_ushort(hy) << 16) | __bfloat16_as_ushort(hx);
}
__device__ __forceinline__ unsigned pack_lo2(float x, float y) {
    __nv_bfloat16 hx = __float2bfloat16(x), hy = __float2bfloat16(y);
    float lx = x - __bfloat162float(hx), ly = y - __bfloat162float(hy);
    __nv_bfloat16 bx = __float2bfloat16(lx), by = __float2bfloat16(ly);
    return ((unsigned)__bfloat16_as_ushort(by) << 16) | __bfloat16_as_ushort(bx);
}

// ---------------- grid barrier (atomic form, used by prep only) ------------
__device__ __forceinline__ void grid_bar_n(int nblk) {
    __syncthreads();
    if (threadIdx.x == 0) {
        unsigned gen = *(volatile unsigned*)&g_barg;
        __threadfence();
        if (atomicAdd(&g_barc, 1u) == (unsigned)nblk - 1) {
            atomicExch(&g_barc, 0u);
            __threadfence();
            *(volatile unsigned*)&g_barg = gen + 1;
        } else {
            while (*(volatile unsigned*)&g_barg == gen) { }
        }
        __threadfence();
    }
    __syncthreads();
}

// ---------------- fused prep ----------------
__global__ void __launch_bounds__(256, 1) prep_kernel(
    const float* __restrict__ x, const float* __restrict__ gamma,
    const float* __restrict__ beta, const float* __restrict__ W_in,
    const float* __restrict__ b_in) {
    int tid = threadIdx.x;
    int blk = blockIdx.x;
    int warp = tid >> 5, lane = tid & 31;

    // reset chain barrier state (graph-replay safe; stream-ordered before chain)
    if (blk == 0) {
        if (tid < CB) g_cflag[tid] = 0u;
        if (tid == 0) g_cgen = 0u;
    }

    {
        float s1[3][4], s2[3][4];
        #pragma unroll
        for (int g = 0; g < 3; g++)
            #pragma unroll
            for (int i = 0; i < 4; i++) { s1[g][i] = 0.f; s2[g][i] = 0.f; }
        int row0 = blk * 64;
        for (int r = 0; r < 64; r++) {
            const float* xr = x + (size_t)(row0 + r) * NIN;
            #pragma unroll
            for (int g = 0; g < 3; g++) {
                float4 v = *(const float4*)&xr[g * 1024 + tid * 4];
                s1[g][0] += v.x; s2[g][0] += v.x * v.x;
                s1[g][1] += v.y; s2[g][1] += v.y * v.y;
                s1[g][2] += v.z; s2[g][2] += v.z * v.z;
                s1[g][3] += v.w; s2[g][3] += v.w * v.w;
            }
        }
        #pragma unroll
        for (int g = 0; g < 3; g++) {
            *(float4*)&g_px1[blk * NIN + g * 1024 + tid * 4] =
                make_float4(s1[g][0], s1[g][1], s1[g][2], s1[g][3]);
            *(float4*)&g_px2[blk * NIN + g * 1024 + tid * 4] =
                make_float4(s2[g][0], s2[g][1], s2[g][2], s2[g][3]);
        }
    }
    grid_bar_n(PB);
    {
        #pragma unroll
        for (int cc = 0; cc < 3; cc++) {
            int col = blk * 24 + warp * 3 + cc;
            float a = 0.f, b = 0.f;
            #pragma unroll
            for (int q = 0; q < 4; q++) {
                a += g_px1[(lane + q * 32) * NIN + col];
                b += g_px2[(lane + q * 32) * NIN + col];
            }
            #pragma unroll
            for (int o = 16; o; o >>= 1) {
                a += __shfl_xor_sync(~0u, a, o);
                b += __shfl_xor_sync(~0u, b, o);
            }
            if (lane == 0) {
                float mean = a * (1.f / BATCH);
                float var = b * (1.f / BATCH) - mean * mean;
                float rstd = rsqrtf(var + BN_EPS);
                float sc = rstd * gamma[col];
                g_scale[col] = sc;
                g_shift[col] = beta[col] - mean * sc;
            }
        }
    }
    grid_bar_n(PB);
    {
        __shared__ float sred[4][64];
        int j = tid & 63, grp = tid >> 6;
        int k = j >> 5, d = j & 31;
        float bias = 0.f;
        #pragma unroll
        for (int p = 0; p < 6; p++) {
            int c = blk * 24 + grp * 6 + p;
            float wraw = W_in[(size_t)k * NIN * D + c * D + d];
            float w = g_scale[c] * wraw;
            __nv_bfloat16 h = __float2bfloat16(w);
            g_WpH[c * 64 + j] = h;
            g_WpL[c * 64 + j] = __float2bfloat16(w - __bfloat162float(h));
            bias += g_shift[c] * wraw;
        }
        sred[grp][j] = bias;
        __syncthreads();
        if (tid < 64)
            g_bpart[blk * 64 + tid] =
                sred[0][tid] + sred[1][tid] + sred[2][tid] + sred[3][tid];
    }
    grid_bar_n(PB);
    if (blk == 0) {
        __shared__ float sred2[4][64];
        int j = tid & 63, grp = tid >> 6;
        float s = 0.f;
        #pragma unroll 8
        for (int b = grp; b < PB; b += 4) s += g_bpart[b * 64 + j];
        sred2[grp][j] = s;
        __syncthreads();
        if (tid < 64)
            g_bp[tid] = b_in[tid] +
                sred2[0][tid] + sred2[1][tid] + sred2[2][tid] + sred2[3][tid];
    }
}

__global__ void woutfold_kernel(const float* __restrict__ Wout) {
    int n = blockIdx.x * 256 + threadIdx.x;
    #pragma unroll 8
    for (int k = 0; k < 64; k++) {
        int bank = k >> 5, d = k & 31;
        float w = (n < NOUT) ? Wout[(size_t)bank * D * NOUT + d * NOUT + n] : 0.f;
        __nv_bfloat16 h = __float2bfloat16(w);
        g_WoutH[k * 1024 + n] = h;
        g_WoutL[k * 1024 + n] = __float2bfloat16(w - __bfloat162float(h));
    }
}

// ---------------- input GEMM (unchanged) ----------------
#define APAD 40
#define BPAD 72
__global__ void __launch_bounds__(256) gemm_in_tc(const float* __restrict__ x) {
    __shared__ __nv_bfloat16 Ah[2][64 * APAD];
    __shared__ __nv_bfloat16 Al[2][64 * APAD];
    __shared__ __nv_bfloat16 Bh[2][32 * BPAD];
    __shared__ __nv_bfloat16 Bl[2][32 * BPAD];
    int tid = threadIdx.x;
    int w = tid >> 5, l = tid & 31;
    int wm = w & 3, wn = w >> 2;
    int rowBase = blockIdx.x * 64;

    int a_r0 = tid >> 3;
    int a_k4 = (tid & 7) * 4;
    int b_kk = tid >> 3;
    int b_n8 = (tid & 7) * 8;

    float4 pa0, pa1;
    uint4 pbh, pbl;
    pa0 = *(const float4*)&x[(size_t)(rowBase + a_r0) * NIN + a_k4];
    pa1 = *(const float4*)&x[(size_t)(rowBase + a_r0 + 32) * NIN + a_k4];
    pbh = *(const uint4*)&g_WpH[b_kk * 64 + b_n8];
    pbl = *(const uint4*)&g_WpL[b_kk * 64 + b_n8];
    {
        uint2 h0, l0;
        h0.x = pack_hi2(pa0.x, pa0.y); h0.y = pack_hi2(pa0.z, pa0.w);
        l0.x = pack_lo2(pa0.x, pa0.y); l0.y = pack_lo2(pa0.z, pa0.w);
        *(uint2*)&Ah[0][a_r0 * APAD + a_k4] = h0;
        *(uint2*)&Al[0][a_r0 * APAD + a_k4] = l0;
        h0.x = pack_hi2(pa1.x, pa1.y); h0.y = pack_hi2(pa1.z, pa1.w);
        l0.x = pack_lo2(pa1.x, pa1.y); l0.y = pack_lo2(pa1.z, pa1.w);
        *(uint2*)&Ah[0][(a_r0 + 32) * APAD + a_k4] = h0;
        *(uint2*)&Al[0][(a_r0 + 32) * APAD + a_k4] = l0;
        *(uint4*)&Bh[0][b_kk * BPAD + b_n8] = pbh;
        *(uint4*)&Bl[0][b_kk * BPAD + b_n8] = pbl;
    }
    __syncthreads();

    float c[4][4];
    #pragma unroll
    for (int i = 0; i < 4; i++)
        #pragma unroll
        for (int j = 0; j < 4; j++) c[i][j] = 0.f;

    int a_row = wm * 16 + (l & 7) + ((l >> 3) & 1) * 8;
    int a_kof = (l >> 4) * 8;
    int b_k = (l & 7) + ((l >> 3) & 1) * 8;
    int b_n = (l >> 4) * 8;

    for (int kt = 0; kt < 96; kt++) {
        int cur = kt & 1, nxt = cur ^ 1;
        if (kt < 95) {
            int kb = (kt + 1) * 32;
            pa0 = *(const float4*)&x[(size_t)(rowBase + a_r0) * NIN + kb + a_k4];
            pa1 = *(const float4*)&x[(size_t)(rowBase + a_r0 + 32) * NIN + kb + a_k4];
            pbh = *(const uint4*)&g_WpH[(kb + b_kk) * 64 + b_n8];
            pbl = *(const uint4*)&g_WpL[(kb + b_kk) * 64 + b_n8];
        }
        unsigned ahb = smem_u32(Ah[cur]), alb = smem_u32(Al[cur]);
        unsigned bhb = smem_u32(Bh[cur]), blb = smem_u32(Bl[cur]);
        #pragma unroll
        for (int ks = 0; ks < 2; ks++) {
            int k0 = ks * 16;
            unsigned a_off = (unsigned)(a_row * (APAD * 2) + (k0 + a_kof) * 2);
            unsigned ah[4], al[4];
            ldsm_x4(ah[0], ah[1], ah[2], ah[3], ahb + a_off);
            ldsm_x4(al[0], al[1], al[2], al[3], alb + a_off);
            #pragma unroll
            for (int g = 0; g < 2; g++) {
                int n0 = wn * 32 + g * 16;
                unsigned b_off = (unsigned)((k0 + b_k) * (BPAD * 2) + (n0 + b_n) * 2);
                unsigned h0, h1, h2, h3, q0, q1, q2, q3;
                ldsm_x4_t(h0, h1, h2, h3, bhb + b_off);
                ldsm_x4_t(q0, q1, q2, q3, blb + b_off);
                mma_bf16(c[2 * g],     ah, h0, h1);
                mma_bf16(c[2 * g + 1], ah, h2, h3);
                mma_bf16(c[2 * g],     ah, q0, q1);
                mma_bf16(c[2 * g + 1], ah, q2, q3);
                mma_bf16(c[2 * g],     al, h0, h1);
                mma_bf16(c[2 * g + 1], al, h2, h3);
            }
        }
        if (kt < 95) {
            uint2 h0, l0;
            h0.x = pack_hi2(pa0.x, pa0.y); h0.y = pack_hi2(pa0.z, pa0.w);
            l0.x = pack_lo2(pa0.x, pa0.y); l0.y = pack_lo2(pa0.z, pa0.w);
            *(uint2*)&Ah[nxt][a_r0 * APAD + a_k4] = h0;
            *(uint2*)&Al[nxt][a_r0 * APAD + a_k4] = l0;
            h0.x = pack_hi2(pa1.x, pa1.y); h0.y = pack_hi2(pa1.z, pa1.w);
            l0.x = pack_lo2(pa1.x, pa1.y); l0.y = pack_lo2(pa1.z, pa1.w);
            *(uint2*)&Ah[nxt][(a_r0 + 32) * APAD + a_k4] = h0;
            *(uint2*)&Al[nxt][(a_r0 + 32) * APAD + a_k4] = l0;
            *(uint4*)&Bh[nxt][b_kk * BPAD + b_n8] = pbh;
            *(uint4*)&Bl[nxt][b_kk * BPAD + b_n8] = pbl;
        }
        __syncthreads();
    }
    int r0 = rowBase + wm * 16 + (l >> 2);
    #pragma unroll
    for (int nb = 0; nb < 4; nb++) {
        int col = wn * 32 + nb * 8 + (l & 3) * 2;
        float2 bp = *(const float2*)&g_bp[col];
        float2 v0, v1;
        v0.x = fmaxf(c[nb][0] + bp.x, 0.f);
        v0.y = fmaxf(c[nb][1] + bp.y, 0.f);
        v1.x = fmaxf(c[nb][2] + bp.x, 0.f);
        v1.y = fmaxf(c[nb][3] + bp.y, 0.f);
        if (col < 32) {
            *(float2*)&g_in0[r0 * D + col] = v0;
            *(float2*)&g_in0[(r0 + 8) * D + col] = v1;
        } else {
            *(float2*)&g_in1[r0 * D + col - 32] = v0;
            *(float2*)&g_in1[(r0 + 8) * D + col - 32] = v1;
        }
    }
}

// ---------------- pipelined bank-chain kernel, 256 threads, 2r x 4c --------
// Per thread: rows r0,r0+1 (rg=tid>>3) x cols j0..j0+3 (cg=tid&7).
#define EDGE_ACC(E, SLOT)                                                     \
    do {                                                                      \
        const float* wp = Wd + (E) * 1024 + j0;                               \
        const float* wgp = Wg + (E) * 32;                                     \
        float4 b4 = __ldg((const float4*)&bd[(E) * 32 + j0]);                 \
        float d00 = b4.x, d01 = b4.y, d02 = b4.z, d03 = b4.w;                 \
        float d10 = b4.x, d11 = b4.y, d12 = b4.z, d13 = b4.w;                 \
        float g0 = 0.f, g1 = 0.f;                                             \
        _Pragma("unroll")                                                     \
        for (int k = 0; k < 32; k++) {                                        \
            float2 a2 = *(const float2*)&actT[(SLOT)][k][r0];                 \
            float4 w4 = __ldg((const float4*)&wp[k * 32]);                    \
            float wgk = __ldg(&wgp[k]);                                       \
            d00 += a2.x * w4.x; d01 += a2.x * w4.y;                           \
            d02 += a2.x * w4.z; d03 += a2.x * w4.w;                           \
            d10 += a2.y * w4.x; d11 += a2.y * w4.y;                           \
            d12 += a2.y * w4.z; d13 += a2.y * w4.w;                           \
            g0 += a2.x * wgk; g1 += a2.y * wgk;                               \
        }                                                                     \
        g0 = fminf(fmaxf(g0, 0.f), 1.f);                                      \
        g1 = fminf(fmaxf(g1, 0.f), 1.f);                                      \
        if (cg == 0) { stg[r0] += g0; stg[r0 + 1] += g1; }                    \
        n00 += g0 * d00; n01 += g0 * d01; n02 += g0 * d02; n03 += g0 * d03;   \
        n10 += g1 * d10; n11 += g1 * d11; n12 += g1 * d12; n13 += g1 * d13;   \
    } while (0)

__global__ void __launch_bounds__(256, 1) chain_kernel(
    const float* __restrict__ Wg, const float* __restrict__ Wd,
    const float* __restrict__ bd, float* __restrict__ tg) {
    __shared__ __align__(16) float actT[4][32][68];
    __shared__ float stg[64];
    __shared__ float smean[32], srstd[32];
    __shared__ float red1[8][32], red2[8][32];

    int tid = threadIdx.x;
    int blk = blockIdx.x;
    int rowBase = blk * 64;
    int rg = tid >> 3, r0 = rg * 2;
    int cg = tid & 7, j0 = cg * 4;
    int warp = tid >> 5, lane = tid & 31;
    int nd = tid >> 3, nrg = (tid & 7) * 8;
    if (tid < 64) stg[tid] = 0.f;

    float acc00, acc01, acc02, acc03, acc10, acc11, acc12, acc13;
    {
        float4 v0 = *(const float4*)&g_in0[(rowBase + r0) * D + j0];
        float4 v1 = *(const float4*)&g_in0[(rowBase + r0 + 1) * D + j0];
        acc00 = v0.x; acc01 = v0.y; acc02 = v0.z; acc03 = v0.w;
        acc10 = v1.x; acc11 = v1.y; acc12 = v1.z; acc13 = v1.w;
    }
    __syncthreads();

    for (int t = 0; t < 16; t++) {
        int slot_t = t & 3;
        // 1. relu + store + warp-shuffle stats partials
        float v00 = fmaxf(acc00, 0.f), v01 = fmaxf(acc01, 0.f);
        float v02 = fmaxf(acc02, 0.f), v03 = fmaxf(acc03, 0.f);
        float v10 = fmaxf(acc10, 0.f), v11 = fmaxf(acc11, 0.f);
        float v12 = fmaxf(acc12, 0.f), v13 = fmaxf(acc13, 0.f);
        *(float2*)&actT[slot_t][j0][r0]     = make_float2(v00, v10);
        *(float2*)&actT[slot_t][j0 + 1][r0] = make_float2(v01, v11);
        *(float2*)&actT[slot_t][j0 + 2][r0] = make_float2(v02, v12);
        *(float2*)&actT[slot_t][j0 + 3][r0] = make_float2(v03, v13);
        float s1c[4], s2c[4];
        s1c[0] = v00 + v10; s2c[0] = v00 * v00 + v10 * v10;
        s1c[1] = v01 + v11; s2c[1] = v01 * v01 + v11 * v11;
        s1c[2] = v02 + v12; s2c[2] = v02 * v02 + v12 * v12;
        s1c[3] = v03 + v13; s2c[3] = v03 * v03 + v13 * v13;
        #pragma unroll
        for (int c = 0; c < 4; c++) {
            s1c[c] += __shfl_xor_sync(~0u, s1c[c], 8);
            s2c[c] += __shfl_xor_sync(~0u, s2c[c], 8);
            s1c[c] += __shfl_xor_sync(~0u, s1c[c], 16);
            s2c[c] += __shfl_xor_sync(~0u, s2c[c], 16);
        }
        if (lane < 8) {
            *(float4*)&red1[warp][lane * 4] = make_float4(s1c[0], s1c[1], s1c[2], s1c[3]);
            *(float4*)&red2[warp][lane * 4] = make_float4(s2c[0], s2c[1], s2c[2], s2c[3]);
        }
        __syncthreads();
        if (warp == 0) {
            float s1 = 0.f, s2 = 0.f;
            #pragma unroll
            for (int g = 0; g < 8; g++) { s1 += red1[g][lane]; s2 += red2[g][lane]; }
            g_p1s[(t * CB + blk) * 32 + lane] = s1;
            g_p2s[(t * CB + blk) * 32 + lane] = s2;
        }
        __syncthreads();
        // 2. barrier ARRIVE: plain store of own flag (no atomic serialization)
        if (tid == 0) {
            __threadfence();
            *(volatile unsigned*)&g_cflag[blk] = (unsigned)(t + 1);
        }
        // 3. EARLY edges for bank tt = t+1 (sources already normalized)
        int tt = t + 1;
        float n00 = 0.f, n01 = 0.f, n02 = 0.f, n03 = 0.f;
        float n10 = 0.f, n11 = 0.f, n12 = 0.f, n13 = 0.f;
        int tec = 0, teb = 0, ts0 = 0;
        if (tt < 16) {
            if (tt == 1) {
                float4 v0 = *(const float4*)&g_in1[(rowBase + r0) * D + j0];
                float4 v1 = *(const float4*)&g_in1[(rowBase + r0 + 1) * D + j0];
                n00 = v0.x; n01 = v0.y; n02 = v0.z; n03 = v0.w;
                n10 = v1.x; n11 = v1.y; n12 = v1.z; n13 = v1.w;
            }
            tec = (tt < 4) ? tt : 4;
            ts0 = (tt - 4 < 0) ? 0 : tt - 4;
            teb = (tt <= 1) ? 0 : (tt == 2) ? 1 : (tt == 3) ? 3 : (tt == 4) ? 6
                                : 10 + (tt - 5) * 4;
            for (int ei = 0; ei < tec - 1; ei++) {
                int e = teb + ei, slot = (ts0 + ei) & 3;
                EDGE_ACC(e, slot);
            }
        }
        // 4. barrier WAIT (flag-tree: block 0 detects, publishes release)
        if (blk == 0) {
            if (tid < CB) {
                while (*(volatile unsigned*)&g_cflag[tid] < (unsigned)(t + 1)) { }
            }
            __syncthreads();
            if (tid == 0) {
                __threadfence();
                *(volatile unsigned*)&g_cgen = (unsigned)(t + 1);
            }
        } else {
            if (tid == 0) {
                while (*(volatile unsigned*)&g_cgen < (unsigned)(t + 1)) { }
                __threadfence();
            }
        }
        __syncthreads();
        // 5. finalize stats for bank t (16 partials per warp, L2 reads)
        {
            float s1 = 0.f, s2 = 0.f;
            #pragma unroll
            for (int q = 0; q < 16; q++) {
                int b = warp + q * 8;
                s1 += __ldcg(&g_p1s[(t * CB + b) * 32 + lane]);
                s2 += __ldcg(&g_p2s[(t * CB + b) * 32 + lane]);
            }
            red1[warp][lane] = s1;
            red2[warp][lane] = s2;
        }
        __syncthreads();
        if (warp == 0) {
            float s1 = 0.f, s2 = 0.f;
            #pragma unroll
            for (int g = 0; g < 8; g++) { s1 += red1[g][lane]; s2 += red2[g][lane]; }
            float mean = s1 * (1.f / BATCH);
            float var = s2 * (1.f / BATCH) - mean * mean;
            smean[lane] = mean;
            srstd[lane] = rsqrtf(var + BN_EPS);
        }
        __syncthreads();
        // 6. normalize slot_t in place (+ export bf16 for banks 14/15)
        {
            float m = smean[nd], r = srstd[nd];
            #pragma unroll
            for (int q2 = 0; q2 < 2; q2++) {
                float4 vv = *(float4*)&actT[slot_t][nd][nrg + q2 * 4];
                vv.x = (vv.x - m) * r; vv.y = (vv.y - m) * r;
                vv.z = (vv.z - m) * r; vv.w = (vv.w - m) * r;
                *(float4*)&actT[slot_t][nd][nrg + q2 * 4] = vv;
                if (t >= 14) {
                    int krow = (t - 14) * 32 + nd;
                    uint2 hv, lv;
                    hv.x = pack_hi2(vv.x, vv.y); hv.y = pack_hi2(vv.z, vv.w);
                    lv.x = pack_lo2(vv.x, vv.y); lv.y = pack_lo2(vv.z, vv.w);
                    *(uint2*)&g_preTH[krow * BATCH + rowBase + nrg + q2 * 4] = hv;
                    *(uint2*)&g_preTL[krow * BATCH + rowBase + nrg + q2 * 4] = lv;
                }
            }
        }
        __syncthreads();
        // 7. LATE edge (source t, just normalized)
        if (tt < 16) {
            int e = teb + tec - 1;
            EDGE_ACC(e, slot_t);
        }
        acc00 = n00; acc01 = n01; acc02 = n02; acc03 = n03;
        acc10 = n10; acc11 = n11; acc12 = n12; acc13 = n13;
    }
    __syncthreads();
    if (tid < 64) tg[rowBase + tid] = stg[tid];
}

// ---------------- output GEMM (unchanged) ----------------
#define ATM 72
#define AST 72
__global__ void __launch_bounds__(256) gemm_out_tc(float* __restrict__ out) {
    __shared__ __nv_bfloat16 ATh[64 * ATM];
    __shared__ __nv_bfloat16 ATl[64 * ATM];
    __shared__ __nv_bfloat16 Bh[64 * AST];
    __shared__ __nv_bfloat16 Bl[64 * AST];
    int tid = threadIdx.x;
    int w = tid >> 5, l = tid & 31;
    int wm = w & 3, wn = w >> 2;
    int rowBase = blockIdx.x * 64;
    int colBase = blockIdx.y * 64;
    unsigned ah_b = smem_u32(ATh), al_b = smem_u32(ATl);
    unsigned bh_b = smem_u32(Bh), bl_b = smem_u32(Bl);

    #pragma unroll
    for (int p = 0; p < 2; p++) {
        int idx = p * 256 + tid;
        int k = idx >> 3;
        int m8 = (idx & 7) * 8;
        *(uint4*)&ATh[k * ATM + m8] = *(const uint4*)&g_preTH[k * BATCH + rowBase + m8];
        *(uint4*)&ATl[k * ATM + m8] = *(const uint4*)&g_preTL[k * BATCH + rowBase + m8];
    }
    #pragma unroll
    for (int p = 0; p < 2; p++) {
        int idx = p * 256 + tid;
        int k = idx >> 3;
        int n8 = (idx & 7) * 8;
        *(uint4*)&Bh[k * AST + n8] = *(const uint4*)&g_WoutH[k * 1024 + colBase + n8];
        *(uint4*)&Bl[k * AST + n8] = *(const uint4*)&g_WoutL[k * 1024 + colBase + n8];
    }
    __syncthreads();

    float c[4][4];
    #pragma unroll
    for (int i = 0; i < 4; i++)
        #pragma unroll
        for (int j = 0; j < 4; j++) c[i][j] = 0.f;

    int a_k = (l & 7) + (l >> 4) * 8;
    int a_m = wm * 16 + ((l >> 3) & 1) * 8;
    int b_k = (l & 7) + ((l >> 3) & 1) * 8;
    int b_n = (l >> 4) * 8;

    #pragma unroll
    for (int ks = 0; ks < 4; ks++) {
        int k0 = ks * 16;
        unsigned a_off = (unsigned)((k0 + a_k) * (ATM * 2) + a_m * 2);
        unsigned ah[4], al[4];
        ldsm_x4_t(ah[0], ah[1], ah[2], ah[3], ah_b + a_off);
        ldsm_x4_t(al[0], al[1], al[2], al[3], al_b + a_off);
        #pragma unroll
        for (int g = 0; g < 2; g++) {
            int n0 = wn * 32 + g * 16;
            unsigned b_off = (unsigned)((k0 + b_k) * (AST * 2) + (n0 + b_n) * 2);
            unsigned h0, h1, h2, h3, q0, q1, q2, q3;
            ldsm_x4_t(h0, h1, h2, h3, bh_b + b_off);
            ldsm_x4_t(q0, q1, q2, q3, bl_b + b_off);
            mma_bf16(c[2 * g],     ah, h0, h1);
            mma_bf16(c[2 * g + 1], ah, h2, h3);
            mma_bf16(c[2 * g],     ah, q0, q1);
            mma_bf16(c[2 * g + 1], ah, q2, q3);
            mma_bf16(c[2 * g],     al, h0, h1);
            mma_bf16(c[2 * g + 1], al, h2, h3);
        }
    }
    int r0 = rowBase + wm * 16 + (l >> 2);
    #pragma unroll
    for (int nb = 0; nb < 4; nb++) {
        int col = colBase + wn * 32 + nb * 8 + (l & 3) * 2;
        if (col < NOUT) {
            float2 v0 = make_float2(c[nb][0], c[nb][1]);
            float2 v1 = make_float2(c[nb][2], c[nb][3]);
            *(float2*)&out[(size_t)r0 * NOUT + col] = v0;
            *(float2*)&out[(size_t)(r0 + 8) * NOUT + col] = v1;
        }
    }
}

// ---------------- launch ----------------
extern "C" void kernel_launch(void* const* d_in, const int* in_sizes, int n_in,
                              void* d_out, int out_size) {
    const float* x     = (const float*)d_in[0];
    const float* gamma = (const float*)d_in[1];
    const float* beta  = (const float*)d_in[2];
    const float* W_in  = (const float*)d_in[3];
    const float* b_in  = (const float*)d_in[4];
    const float* Wg    = (const float*)d_in[5];
    const float* Wd    = (const float*)d_in[6];
    const float* bd    = (const float*)d_in[7];
    const float* Wout  = (const float*)d_in[8];
    float* out = (float*)d_out;

    float* tg;
    if (out_size >= BATCH * NOUT + BATCH) {
        tg = out + (size_t)BATCH * NOUT;
    } else {
        void* p = nullptr;
        cudaGetSymbolAddress(&p, g_tg_fallback);
        tg = (float*)p;
    }

    prep_kernel<<<PB, 256>>>(x, gamma, beta, W_in, b_in);
    woutfold_kernel<<<4, 256>>>(Wout);
    gemm_in_tc<<<128, 256>>>(x);
    chain_kernel<<<CB, 256>>>(Wg, Wd, bd, tg);   // 4th launch -> ncu target
    gemm_out_tc<<<dim3(128, 16), 256>>>(out);
}